// round 14
// baseline (speedup 1.0000x reference)
#include <cuda_runtime.h>
#include <cuda_fp16.h>
#include <cstdint>

#define BATCH 4
#define CH    256
#define NPIX  4096
#define NGRP  32
#define CPG   8

// ---------------------------------------------------------------------------
// Scratch (device globals)
// ---------------------------------------------------------------------------
__device__ __half g_ht[BATCH * NPIX * CH];           // Hand^T fp16 [b][n][c]
__device__ __half g_ut[BATCH * NPIX * CH];           // U^T    fp16 [b][n][c]
__device__ __half g_wh[CH * CH];                     // WH fp16 [o][c]
__device__ __half g_wu[CH * CH];                     // WU fp16 [o][c]
__device__ __half g_qt[BATCH * NPIX * CH];           // q^T fp16 [b][n][c]
__device__ __half g_kt[BATCH * NPIX * CH];           // k^T fp16 [b][m][c]
__device__ __half g_ub[BATCH * CH * NPIX];           // U fp16   [b][c][m]
__device__ __half g_P [(size_t)BATCH * NPIX * NPIX]; // exp(s - mx_tile) fp16
__device__ float  g_pmx  [BATCH * NPIX * 32];
__device__ float  g_psum [BATCH * NPIX * 32];
__device__ float  g_scale[BATCH * NPIX * 32];

// ---------------------------------------------------------------------------
// Helpers
// ---------------------------------------------------------------------------
__device__ __forceinline__ float warpMax(float v) {
    #pragma unroll
    for (int o = 16; o > 0; o >>= 1)
        v = fmaxf(v, __shfl_xor_sync(0xffffffffu, v, o));
    return v;
}
__device__ __forceinline__ float warpSum(float v) {
    #pragma unroll
    for (int o = 16; o > 0; o >>= 1)
        v += __shfl_xor_sync(0xffffffffu, v, o);
    return v;
}
// fp16 m16n8k16, fp32 accumulate
__device__ __forceinline__ void mma_f16(float* c, const unsigned* a, const unsigned* b) {
    asm volatile(
        "mma.sync.aligned.m16n8k16.row.col.f32.f16.f16.f32 "
        "{%0,%1,%2,%3},{%4,%5,%6,%7},{%8,%9},{%0,%1,%2,%3};"
        : "+f"(c[0]), "+f"(c[1]), "+f"(c[2]), "+f"(c[3])
        : "r"(a[0]), "r"(a[1]), "r"(a[2]), "r"(a[3]), "r"(b[0]), "r"(b[1]));
}
__device__ __forceinline__ void ldsm_x4(unsigned* r, uint32_t addr) {
    asm volatile("ldmatrix.sync.aligned.m8n8.x4.shared.b16 {%0,%1,%2,%3}, [%4];"
                 : "=r"(r[0]), "=r"(r[1]), "=r"(r[2]), "=r"(r[3]) : "r"(addr));
}
__device__ __forceinline__ uint32_t smem_u32(const void* p) {
    uint32_t a;
    asm("{ .reg .u64 t; cvta.to.shared.u64 t, %1; cvt.u32.u64 %0, t; }" : "=r"(a) : "l"(p));
    return a;
}
__device__ __forceinline__ void cpa16(uint32_t dst, const void* src) {
    asm volatile("cp.async.cg.shared.global [%0], [%1], 16;" :: "r"(dst), "l"(src));
}
#define CPA_COMMIT() asm volatile("cp.async.commit_group;" ::: "memory")
#define CPA_WAIT2()  asm volatile("cp.async.wait_group 2;" ::: "memory")
#define CPA_WAIT1()  asm volatile("cp.async.wait_group 1;" ::: "memory")
#define CPA_WAIT0()  asm volatile("cp.async.wait_group 0;" ::: "memory")

#define PW        40
#define STG_BYTES (128 * PW * 2)   // 10240 B per 128-row stage
#define NSTG      4                // 4 buffers, prefetch depth 3
#define PTP       136              // P staging tile pitch (halfs): bank = 4*fr + (lane&3)
#define LOG2E     1.4426950408889634f

// ---------------------------------------------------------------------------
// 0a) Weights fp32 -> fp16
// ---------------------------------------------------------------------------
__global__ __launch_bounds__(256)
void wconv_kernel(const float* __restrict__ wh, const float* __restrict__ wu)
{
    const int i = (blockIdx.x * 256 + threadIdx.x) * 4;
    const float* src;
    __half* dst;
    int j = i;
    if (i < CH * CH) { src = wh; dst = g_wh; }
    else             { src = wu; dst = g_wu; j = i - CH * CH; }
    float4 v = *(const float4*)(src + j);
    __half2 h0 = __floats2half2_rn(v.x, v.y);
    __half2 h1 = __floats2half2_rn(v.z, v.w);
    uint2 w;
    w.x = *(unsigned*)&h0;
    w.y = *(unsigned*)&h1;
    *(uint2*)(dst + j) = w;
}

// ---------------------------------------------------------------------------
// 0b) Transpose inputs + fp16 convert: Hand/U [c][n] -> g_ht/g_ut [n][c]
//     For U (which==1), also emit the straight-layout fp16 copy (g_ub).
// ---------------------------------------------------------------------------
__global__ __launch_bounds__(256)
void tin_kernel(const float* __restrict__ Hand, const float* __restrict__ U)
{
    __shared__ float t[32][33];
    const int which = blockIdx.z & 1;
    const int b     = blockIdx.z >> 1;
    const float* src = which ? U : Hand;
    __half* dst = which ? g_ut : g_ht;

    const int n0 = blockIdx.x * 32;
    const int c0 = blockIdx.y * 32;
    const int tx = threadIdx.x & 31;
    const int ty = threadIdx.x >> 5;

    const float* sp = src + (size_t)b * CH * NPIX + (size_t)(c0 + ty) * NPIX + n0 + tx;
    #pragma unroll
    for (int j = 0; j < 4; ++j) {
        const float v = sp[(size_t)j * 8 * NPIX];
        t[ty + j * 8][tx] = v;
        if (which) {
            g_ub[(size_t)b * CH * NPIX + (size_t)(c0 + ty + j * 8) * NPIX + n0 + tx] =
                __float2half(v);
        }
    }
    __syncthreads();

    #pragma unroll
    for (int j = 0; j < 4; ++j) {
        size_t o = (size_t)b * NPIX * CH + (size_t)(n0 + ty + j * 8) * CH + c0 + tx;
        dst[o] = __float2half(t[tx][ty + j * 8]);
    }
}

// ---------------------------------------------------------------------------
// 1) Projection fp16 GEMM: dst[n][o] = Xt[n][:]·W[o][:] + bias[o]
//    Single launch: blockIdx.z = b + BATCH*which. 4-stage depth-3 pipeline.
// ---------------------------------------------------------------------------
__global__ __launch_bounds__(256, 2)
void proj_f16(const float* __restrict__ biasH, const float* __restrict__ biasU)
{
    extern __shared__ char sm_[];
    __half* As = (__half*)sm_;
    __half* Bs = (__half*)(sm_ + NSTG * STG_BYTES);

    const int which = blockIdx.z >> 2;
    const int b     = blockIdx.z & 3;
    const __half* xt = which ? g_ut : g_ht;
    const __half* wf = which ? g_wu : g_wh;
    const float* bias = which ? biasU : biasH;
    __half* dst = which ? g_kt : g_qt;

    const int o0 = blockIdx.y * 128;
    const int n0 = blockIdx.x * 128;
    const int tid  = threadIdx.x;
    const int lane = tid & 31;
    const int wid  = tid >> 5;
    const int wm   = (wid >> 2) * 64;   // n
    const int wn   = (wid & 3) * 32;    // o

    const int r  = tid >> 1;
    const int hb = (tid & 1) * 16;
    const __half* ag = xt + (size_t)b * NPIX * CH + (size_t)(n0 + r) * CH + hb;
    const __half* bg = wf + (size_t)(o0 + r) * CH + hb;
    const uint32_t as_ = smem_u32(As) + (uint32_t)(r * 80 + hb * 2);
    const uint32_t bs_ = smem_u32(Bs) + (uint32_t)(r * 80 + hb * 2);

    const uint32_t afrag = smem_u32(As)
        + (uint32_t)(((wm + (lane & 15)) * PW + ((lane >> 4) * 8)) * 2);
    const uint32_t bfrag = smem_u32(Bs)
        + (uint32_t)(((wn + ((lane & 16) >> 1) + (lane & 7)) * PW + (lane & 8)) * 2);

    const int KT = CH / 32;  // 8
    #define PJ_ISSUE(kt) do {                                   \
        const uint32_t so = (uint32_t)((kt) % NSTG) * STG_BYTES; \
        cpa16(as_ + so,      ag + (kt) * 32);                   \
        cpa16(as_ + so + 16, ag + (kt) * 32 + 8);               \
        cpa16(bs_ + so,      bg + (kt) * 32);                   \
        cpa16(bs_ + so + 16, bg + (kt) * 32 + 8);               \
        CPA_COMMIT();                                           \
    } while (0)

    PJ_ISSUE(0);
    PJ_ISSUE(1);
    PJ_ISSUE(2);

    float acc[4][4][4];
    #pragma unroll
    for (int i = 0; i < 4; ++i)
        #pragma unroll
        for (int j = 0; j < 4; ++j)
            #pragma unroll
            for (int q = 0; q < 4; ++q) acc[i][j][q] = 0.f;

    #pragma unroll 1
    for (int kt = 0; kt < KT; ++kt) {
        if (kt + 2 < KT)      { CPA_WAIT2(); }
        else if (kt + 1 < KT) { CPA_WAIT1(); }
        else                  { CPA_WAIT0(); }
        __syncthreads();
        if (kt + 3 < KT) PJ_ISSUE(kt + 3);

        const uint32_t so = (uint32_t)(kt % NSTG) * STG_BYTES;
        #pragma unroll
        for (int ks = 0; ks < 2; ++ks) {
            unsigned a[4][4], bb[4][2];
            const uint32_t ko = so + (uint32_t)ks * 32;
            #pragma unroll
            for (int mt = 0; mt < 4; ++mt)
                ldsm_x4(a[mt], afrag + ko + (uint32_t)mt * (16 * PW * 2));
            ldsm_x4(&bb[0][0], bfrag + ko);
            ldsm_x4(&bb[2][0], bfrag + ko + (uint32_t)(16 * PW * 2));
            #pragma unroll
            for (int mt = 0; mt < 4; ++mt)
                #pragma unroll
                for (int nt = 0; nt < 4; ++nt)
                    mma_f16(acc[mt][nt], a[mt], bb[nt]);
        }
    }
    #undef PJ_ISSUE

    const int fr = lane >> 2, fc = (lane & 3) * 2;
    __half* db = dst + (size_t)b * NPIX * CH;
    #pragma unroll
    for (int mt = 0; mt < 4; ++mt) {
        const int row = n0 + wm + mt * 16 + fr;
        #pragma unroll
        for (int nt = 0; nt < 4; ++nt) {
            const int col = o0 + wn + nt * 8 + fc;
            const float bv0 = bias[col];
            const float bv1 = bias[col + 1];
            __half2 h0 = __floats2half2_rn(acc[mt][nt][0] + bv0, acc[mt][nt][1] + bv1);
            __half2 h1 = __floats2half2_rn(acc[mt][nt][2] + bv0, acc[mt][nt][3] + bv1);
            *(__half2*)(db + (size_t)row * CH + col)       = h0;
            *(__half2*)(db + (size_t)(row + 8) * CH + col) = h1;
        }
    }
}

// ---------------------------------------------------------------------------
// 2) Logits GEMM fp16 (LDSM fragments) + fused per-tile softmax (ex2.f16x2)
//    4-stage depth-3 pipeline; P staged in smem, coalesced write-out.
// ---------------------------------------------------------------------------
__global__ __launch_bounds__(256, 2)
void sgemm_f16()
{
    extern __shared__ char sm_[];
    __half* Qs = (__half*)sm_;
    __half* Ks = (__half*)(sm_ + NSTG * STG_BYTES);
    float*  red = (float*)(sm_ + 2 * NSTG * STG_BYTES);   // [128][4]
    __half* Pt = (__half*)sm_;   // P staging tile 128 x PTP (reuses dead pipeline bufs)

    const int m0 = blockIdx.x * 128;
    const int n0 = blockIdx.y * 128;
    const int b  = blockIdx.z;
    const int tid  = threadIdx.x;
    const int lane = tid & 31;
    const int wid  = tid >> 5;
    const int wm   = (wid >> 2) * 64;
    const int wn   = (wid & 3) * 32;

    const int r  = tid >> 1;
    const int hb = (tid & 1) * 16;
    const __half* qg = g_qt + (size_t)b * NPIX * CH + (size_t)(n0 + r) * CH + hb;
    const __half* kg = g_kt + (size_t)b * NPIX * CH + (size_t)(m0 + r) * CH + hb;
    const uint32_t qs = smem_u32(Qs) + (uint32_t)(r * 80 + hb * 2);
    const uint32_t ks_ = smem_u32(Ks) + (uint32_t)(r * 80 + hb * 2);

    const uint32_t afrag = smem_u32(Qs)
        + (uint32_t)(((wm + (lane & 15)) * PW + ((lane >> 4) * 8)) * 2);
    const uint32_t bfrag = smem_u32(Ks)
        + (uint32_t)(((wn + ((lane & 16) >> 1) + (lane & 7)) * PW + (lane & 8)) * 2);

    const int KT = CH / 32;  // 8 stages
    #define SG_ISSUE(kt) do {                                   \
        const uint32_t so = (uint32_t)((kt) % NSTG) * STG_BYTES; \
        cpa16(qs + so,      qg + (kt) * 32);                    \
        cpa16(qs + so + 16, qg + (kt) * 32 + 8);                \
        cpa16(ks_ + so,      kg + (kt) * 32);                   \
        cpa16(ks_ + so + 16, kg + (kt) * 32 + 8);               \
        CPA_COMMIT();                                           \
    } while (0)

    SG_ISSUE(0);
    SG_ISSUE(1);
    SG_ISSUE(2);

    float acc[4][4][4];
    #pragma unroll
    for (int i = 0; i < 4; ++i)
        #pragma unroll
        for (int j = 0; j < 4; ++j)
            #pragma unroll
            for (int q = 0; q < 4; ++q) acc[i][j][q] = 0.f;

    #pragma unroll 1
    for (int kt = 0; kt < KT; ++kt) {
        if (kt + 2 < KT)      { CPA_WAIT2(); }
        else if (kt + 1 < KT) { CPA_WAIT1(); }
        else                  { CPA_WAIT0(); }
        __syncthreads();
        if (kt + 3 < KT) SG_ISSUE(kt + 3);

        const uint32_t so = (uint32_t)(kt % NSTG) * STG_BYTES;
        #pragma unroll
        for (int ks = 0; ks < 2; ++ks) {
            unsigned a[4][4], bb[4][2];
            const uint32_t ko = so + (uint32_t)ks * 32;
            #pragma unroll
            for (int mt = 0; mt < 4; ++mt)
                ldsm_x4(a[mt], afrag + ko + (uint32_t)mt * (16 * PW * 2));
            ldsm_x4(&bb[0][0], bfrag + ko);
            ldsm_x4(&bb[2][0], bfrag + ko + (uint32_t)(16 * PW * 2));
            #pragma unroll
            for (int mt = 0; mt < 4; ++mt)
                #pragma unroll
                for (int nt = 0; nt < 4; ++nt)
                    mma_f16(acc[mt][nt], a[mt], bb[nt]);
        }
    }
    #undef SG_ISSUE

    // ---- fused tile softmax ----
    float rmax[8];
    #pragma unroll
    for (int mt = 0; mt < 4; ++mt)
        #pragma unroll
        for (int h = 0; h < 2; ++h) {
            float v = fmaxf(acc[mt][0][h * 2], acc[mt][0][h * 2 + 1]);
            #pragma unroll
            for (int nt = 1; nt < 4; ++nt)
                v = fmaxf(v, fmaxf(acc[mt][nt][h * 2], acc[mt][nt][h * 2 + 1]));
            rmax[mt * 2 + h] = v;
        }
    #pragma unroll
    for (int s = 0; s < 8; ++s) {
        rmax[s] = fmaxf(rmax[s], __shfl_xor_sync(0xffffffffu, rmax[s], 1));
        rmax[s] = fmaxf(rmax[s], __shfl_xor_sync(0xffffffffu, rmax[s], 2));
    }
    __syncthreads();   // pipeline smem dead beyond this point (Pt reuse is safe)
    if ((lane & 3) == 0) {
        #pragma unroll
        for (int s = 0; s < 8; ++s) {
            const int rr = wm + (s >> 1) * 16 + (lane >> 2) + (s & 1) * 8;
            red[rr * 4 + (wid & 3)] = rmax[s];
        }
    }
    __syncthreads();
    float tmax[8];
    #pragma unroll
    for (int s = 0; s < 8; ++s) {
        const int rr = wm + (s >> 1) * 16 + (lane >> 2) + (s & 1) * 8;
        tmax[s] = fmaxf(fmaxf(red[rr * 4], red[rr * 4 + 1]),
                        fmaxf(red[rr * 4 + 2], red[rr * 4 + 3]));
    }
    __syncthreads();

    // exp via packed half2 ex2 -> smem staging tile (conflict-free STS)
    float rsum[8] = {0.f, 0.f, 0.f, 0.f, 0.f, 0.f, 0.f, 0.f};
    #pragma unroll
    for (int mt = 0; mt < 4; ++mt)
        #pragma unroll
        for (int h = 0; h < 2; ++h) {
            const int slot = mt * 2 + h;
            const int rr = wm + mt * 16 + (lane >> 2) + h * 8;
            const float tmL = tmax[slot] * LOG2E;
            __half* pp = Pt + rr * PTP + wn + (lane & 3) * 2;
            #pragma unroll
            for (int nt = 0; nt < 4; ++nt) {
                const float t0 = fmaf(acc[mt][nt][h * 2],     LOG2E, -tmL);
                const float t1 = fmaf(acc[mt][nt][h * 2 + 1], LOG2E, -tmL);
                __half2 th = __floats2half2_rn(t0, t1);
                unsigned pu;
                asm("ex2.approx.f16x2 %0, %1;" : "=r"(pu) : "r"(*(unsigned*)&th));
                __half2 ph = *(__half2*)&pu;
                float2 pf = __half22float2(ph);
                rsum[slot] += pf.x + pf.y;
                *(__half2*)(pp + nt * 8) = ph;
            }
        }
    #pragma unroll
    for (int s = 0; s < 8; ++s) {
        rsum[s] += __shfl_xor_sync(0xffffffffu, rsum[s], 1);
        rsum[s] += __shfl_xor_sync(0xffffffffu, rsum[s], 2);
    }
    if ((lane & 3) == 0) {
        #pragma unroll
        for (int s = 0; s < 8; ++s) {
            const int rr = wm + (s >> 1) * 16 + (lane >> 2) + (s & 1) * 8;
            red[rr * 4 + (wid & 3)] = rsum[s];
        }
    }
    __syncthreads();   // also orders Pt writes before readback below
    if ((wid & 3) == 0 && (lane & 3) == 0) {
        #pragma unroll
        for (int s = 0; s < 8; ++s) {
            const int rr = wm + (s >> 1) * 16 + (lane >> 2) + (s & 1) * 8;
            const float tot = red[rr * 4] + red[rr * 4 + 1] + red[rr * 4 + 2] + red[rr * 4 + 3];
            const int gi = (b * NPIX + n0 + rr) * 32 + blockIdx.x;
            g_pmx[gi]  = tmax[s];
            g_psum[gi] = tot;
        }
    }

    // coalesced P write-out: each thread handles one 64-col half-row
    {
        const int r2 = tid >> 1;
        const int cb = (tid & 1) * 64;
        const __half* src = Pt + r2 * PTP + cb;
        __half* dstp = g_P + (size_t)b * NPIX * NPIX
                     + (size_t)(n0 + r2) * NPIX + m0 + cb;
        #pragma unroll
        for (int j = 0; j < 8; ++j)
            *(uint4*)(dstp + j * 8) = *(const uint4*)(src + j * 8);
    }
}

// ---------------------------------------------------------------------------
// 3) Combine per-tile stats -> per-(row, m-tile) rescale factor
// ---------------------------------------------------------------------------
__global__ __launch_bounds__(256)
void combine_kernel()
{
    const int row  = blockIdx.x * 8 + (threadIdx.x >> 5);
    const int lane = threadIdx.x & 31;
    const float mx = g_pmx [row * 32 + lane];
    const float sm = g_psum[row * 32 + lane];
    const float M  = warpMax(mx);
    const float e  = __expf(mx - M);
    const float tot = warpSum(sm * e);
    g_scale[row * 32 + lane] = e / tot;
}

// ---------------------------------------------------------------------------
// 4) AV GEMM fp16 (LDSM fragments). 4-stage depth-3 pipeline.
// ---------------------------------------------------------------------------
__global__ __launch_bounds__(256, 2)
void av_f16(float* __restrict__ out)
{
    extern __shared__ char sm_[];
    __half* Us = (__half*)sm_;
    __half* Ps = (__half*)(sm_ + NSTG * STG_BYTES);

    const int n0 = blockIdx.x * 128;
    const int c0 = blockIdx.y * 128;
    const int b  = blockIdx.z;
    const int tid  = threadIdx.x;
    const int lane = tid & 31;
    const int wid  = tid >> 5;
    const int wm   = (wid >> 2) * 64;
    const int wn   = (wid & 3) * 32;

    const int r  = tid >> 1;
    const int hb = (tid & 1) * 16;
    const __half* ug = g_ub + (size_t)b * CH * NPIX   + (size_t)(c0 + r) * NPIX + hb;
    const __half* pg = g_P  + (size_t)b * NPIX * NPIX + (size_t)(n0 + r) * NPIX + hb;
    const uint32_t us = smem_u32(Us) + (uint32_t)(r * 80 + hb * 2);
    const uint32_t ps = smem_u32(Ps) + (uint32_t)(r * 80 + hb * 2);

    const uint32_t afrag = smem_u32(Us)
        + (uint32_t)(((wm + (lane & 15)) * PW + ((lane >> 4) * 8)) * 2);
    const uint32_t bfrag = smem_u32(Ps)
        + (uint32_t)(((wn + ((lane & 16) >> 1) + (lane & 7)) * PW + (lane & 8)) * 2);

    const float* scb = g_scale + (size_t)(b * NPIX + n0) * 32;

    const int KT = NPIX / 32;  // 128 stages
    #define AV_ISSUE(kt) do {                                   \
        const uint32_t so = (uint32_t)((kt) % NSTG) * STG_BYTES; \
        cpa16(us + so,      ug + (kt) * 32);                    \
        cpa16(us + so + 16, ug + (kt) * 32 + 8);                \
        cpa16(ps + so,      pg + (kt) * 32);                    \
        cpa16(ps + so + 16, pg + (kt) * 32 + 8);                \
        CPA_COMMIT();                                           \
    } while (0)

    AV_ISSUE(0);
    AV_ISSUE(1);
    AV_ISSUE(2);

    float acc[4][4][4];
    #pragma unroll
    for (int i = 0; i < 4; ++i)
        #pragma unroll
        for (int j = 0; j < 4; ++j)
            #pragma unroll
            for (int q = 0; q < 4; ++q) acc[i][j][q] = 0.f;

    __half2 sc[4];

    #pragma unroll 1
    for (int kt = 0; kt < KT; ++kt) {
        if ((kt & 3) == 0) {
            #pragma unroll
            for (int nt = 0; nt < 4; ++nt) {
                const int n = wn + nt * 8 + (lane >> 2);
                sc[nt] = __float2half2_rn(scb[n * 32 + (kt >> 2)]);
            }
        }
        if (kt + 2 < KT)      { CPA_WAIT2(); }
        else if (kt + 1 < KT) { CPA_WAIT1(); }
        else                  { CPA_WAIT0(); }
        __syncthreads();
        if (kt + 3 < KT) AV_ISSUE(kt + 3);

        const uint32_t so = (uint32_t)(kt % NSTG) * STG_BYTES;
        #pragma unroll
        for (int ks = 0; ks < 2; ++ks) {
            unsigned a[4][4], bb[4][2];
            const uint32_t ko = so + (uint32_t)ks * 32;
            #pragma unroll
            for (int mt = 0; mt < 4; ++mt)
                ldsm_x4(a[mt], afrag + ko + (uint32_t)mt * (16 * PW * 2));
            ldsm_x4(&bb[0][0], bfrag + ko);
            ldsm_x4(&bb[2][0], bfrag + ko + (uint32_t)(16 * PW * 2));
            #pragma unroll
            for (int nt = 0; nt < 4; ++nt) {
                __half2 b0 = __hmul2(*(__half2*)&bb[nt][0], sc[nt]);
                __half2 b1 = __hmul2(*(__half2*)&bb[nt][1], sc[nt]);
                bb[nt][0] = *(unsigned*)&b0;
                bb[nt][1] = *(unsigned*)&b1;
            }
            #pragma unroll
            for (int mt = 0; mt < 4; ++mt)
                #pragma unroll
                for (int nt = 0; nt < 4; ++nt)
                    mma_f16(acc[mt][nt], a[mt], bb[nt]);
        }
    }
    #undef AV_ISSUE

    const int fr = lane >> 2, fc = (lane & 3) * 2;
    #pragma unroll
    for (int mt = 0; mt < 4; ++mt) {
        const int row = c0 + wm + mt * 16 + fr;
        #pragma unroll
        for (int nt = 0; nt < 4; ++nt) {
            const int col = n0 + wn + nt * 8 + fc;
            float* p0 = out + (size_t)b * CH * NPIX + (size_t)row * NPIX + col;
            float* p1 = p0 + (size_t)8 * NPIX;
            *(float2*)p0 = make_float2(acc[mt][nt][0], acc[mt][nt][1]);
            *(float2*)p1 = make_float2(acc[mt][nt][2], acc[mt][nt][3]);
        }
    }
}

// ---------------------------------------------------------------------------
// 5) GroupNorm(+residual) in place on d_out — 1024 threads/block
// ---------------------------------------------------------------------------
__global__ __launch_bounds__(1024)
void gn_kernel(float* __restrict__ out, const float* __restrict__ Hand,
               const float* __restrict__ gw, const float* __restrict__ gb)
{
    const int b = blockIdx.x >> 5;
    const int g = blockIdx.x & 31;
    const size_t off = (size_t)b * CH * NPIX + (size_t)g * CPG * NPIX;
    float* base = out + off;
    const float* hb = Hand + off;
    const int tid = threadIdx.x;

    float s1 = 0.f, s2 = 0.f;
    #pragma unroll
    for (int i = 0; i < 8; ++i) {
        float4 v = *(const float4*)(base + i * 4096 + tid * 4);
        s1 += v.x + v.y + v.z + v.w;
        s2 += v.x * v.x + v.y * v.y + v.z * v.z + v.w * v.w;
    }
    s1 = warpSum(s1);
    s2 = warpSum(s2);
    __shared__ float a1[32], a2[32];
    if ((tid & 31) == 0) { a1[tid >> 5] = s1; a2[tid >> 5] = s2; }
    __syncthreads();
    __shared__ float mean_s, rstd_s;
    if (tid < 32) {
        float S1 = a1[tid], S2 = a2[tid];
        S1 = warpSum(S1);
        S2 = warpSum(S2);
        if (tid == 0) {
            const float inv  = 1.f / (float)(CPG * NPIX);
            const float mean = S1 * inv;
            const float var  = S2 * inv - mean * mean;
            mean_s = mean;
            rstd_s = rsqrtf(var + 1e-5f);
        }
    }
    __syncthreads();
    const float mean = mean_s, rstd = rstd_s;

    #pragma unroll
    for (int i = 0; i < 8; ++i) {
        const int f = i * 4096 + tid * 4;
        const int c = g * CPG + (f >> 12);
        const float w  = gw[c];
        const float bi = gb[c];
        float4 v = *(const float4*)(base + f);
        float4 h = *(const float4*)(hb + f);
        v.x = (v.x - mean) * rstd * w + bi + h.x;
        v.y = (v.y - mean) * rstd * w + bi + h.y;
        v.z = (v.z - mean) * rstd * w + bi + h.z;
        v.w = (v.w - mean) * rstd * w + bi + h.w;
        *(float4*)(base + f) = v;
    }
}

// ---------------------------------------------------------------------------
extern "C" void kernel_launch(void* const* d_in, const int* in_sizes, int n_in,
                              void* d_out, int out_size)
{
    const float* Hand = (const float*)d_in[0];
    const float* U    = (const float*)d_in[1];
    const float* WHw  = (const float*)d_in[2];
    const float* WHb  = (const float*)d_in[3];
    const float* WUw  = (const float*)d_in[4];
    const float* WUb  = (const float*)d_in[5];
    const float* gnw  = (const float*)d_in[6];
    const float* gnb  = (const float*)d_in[7];
    float* out = (float*)d_out;

    const int pj_smem = 2 * NSTG * STG_BYTES;                // 81920
    const int sg_smem = 2 * NSTG * STG_BYTES + 128 * 4 * 4;  // 83968
    const int av_smem = 2 * NSTG * STG_BYTES;                // 81920
    cudaFuncSetAttribute(proj_f16,  cudaFuncAttributeMaxDynamicSharedMemorySize, pj_smem);
    cudaFuncSetAttribute(sgemm_f16, cudaFuncAttributeMaxDynamicSharedMemorySize, sg_smem);
    cudaFuncSetAttribute(av_f16,    cudaFuncAttributeMaxDynamicSharedMemorySize, av_smem);

    wconv_kernel<<<(2 * CH * CH) / (256 * 4), 256>>>(WHw, WUw);

    dim3 tg(NPIX / 32, CH / 32, BATCH * 2);
    tin_kernel<<<tg, 256>>>(Hand, U);

    dim3 pg(NPIX / 128, CH / 128, BATCH * 2);
    proj_f16<<<pg, 256, pj_smem>>>(WHb, WUb);

    dim3 sg(NPIX / 128, NPIX / 128, BATCH);
    sgemm_f16<<<sg, 256, sg_smem>>>();

    combine_kernel<<<(BATCH * NPIX) / 8, 256>>>();

    dim3 ag(NPIX / 128, CH / 128, BATCH);
    av_f16<<<ag, 256, av_smem>>>(out);

    gn_kernel<<<BATCH * NGRP, 1024>>>(out, Hand, gnw, gnb);
}

// round 15
// speedup vs baseline: 1.0319x; 1.0319x over previous
#include <cuda_runtime.h>
#include <cuda_fp16.h>
#include <cstdint>

#define BATCH 4
#define CH    256
#define NPIX  4096
#define NGRP  32
#define CPG   8

// ---------------------------------------------------------------------------
// Scratch (device globals)
// ---------------------------------------------------------------------------
__device__ __half g_ht[BATCH * NPIX * CH];           // Hand^T fp16 [b][n][c]
__device__ __half g_ut[BATCH * NPIX * CH];           // U^T    fp16 [b][n][c]
__device__ __half g_wh[CH * CH];                     // WH fp16 [o][c]
__device__ __half g_wu[CH * CH];                     // WU fp16 [o][c]
__device__ __half g_qt[BATCH * NPIX * CH];           // q^T fp16 [b][n][c]
__device__ __half g_kt[BATCH * NPIX * CH];           // k^T fp16 [b][m][c]
__device__ __half g_ub[BATCH * CH * NPIX];           // U fp16   [b][c][m]
__device__ __half g_P [(size_t)BATCH * NPIX * NPIX]; // exp(s - mx_tile) fp16
__device__ float  g_pmx  [BATCH * NPIX * 32];
__device__ float  g_psum [BATCH * NPIX * 32];

// ---------------------------------------------------------------------------
// Helpers
// ---------------------------------------------------------------------------
__device__ __forceinline__ float warpMax(float v) {
    #pragma unroll
    for (int o = 16; o > 0; o >>= 1)
        v = fmaxf(v, __shfl_xor_sync(0xffffffffu, v, o));
    return v;
}
__device__ __forceinline__ float warpSum(float v) {
    #pragma unroll
    for (int o = 16; o > 0; o >>= 1)
        v += __shfl_xor_sync(0xffffffffu, v, o);
    return v;
}
// fp16 m16n8k16, fp32 accumulate
__device__ __forceinline__ void mma_f16(float* c, const unsigned* a, const unsigned* b) {
    asm volatile(
        "mma.sync.aligned.m16n8k16.row.col.f32.f16.f16.f32 "
        "{%0,%1,%2,%3},{%4,%5,%6,%7},{%8,%9},{%0,%1,%2,%3};"
        : "+f"(c[0]), "+f"(c[1]), "+f"(c[2]), "+f"(c[3])
        : "r"(a[0]), "r"(a[1]), "r"(a[2]), "r"(a[3]), "r"(b[0]), "r"(b[1]));
}
__device__ __forceinline__ void ldsm_x4(unsigned* r, uint32_t addr) {
    asm volatile("ldmatrix.sync.aligned.m8n8.x4.shared.b16 {%0,%1,%2,%3}, [%4];"
                 : "=r"(r[0]), "=r"(r[1]), "=r"(r[2]), "=r"(r[3]) : "r"(addr));
}
__device__ __forceinline__ uint32_t smem_u32(const void* p) {
    uint32_t a;
    asm("{ .reg .u64 t; cvta.to.shared.u64 t, %1; cvt.u32.u64 %0, t; }" : "=r"(a) : "l"(p));
    return a;
}
__device__ __forceinline__ void cpa16(uint32_t dst, const void* src) {
    asm volatile("cp.async.cg.shared.global [%0], [%1], 16;" :: "r"(dst), "l"(src));
}
#define CPA_COMMIT() asm volatile("cp.async.commit_group;" ::: "memory")
#define CPA_WAIT1()  asm volatile("cp.async.wait_group 1;" ::: "memory")
#define CPA_WAIT0()  asm volatile("cp.async.wait_group 0;" ::: "memory")

#define PW        40
#define STG_BYTES (128 * PW * 2)   // 10240 B per 128-row stage
#define LOG2E     1.4426950408889634f

// ---------------------------------------------------------------------------
// 0a) Weights fp32 -> fp16
// ---------------------------------------------------------------------------
__global__ __launch_bounds__(256)
void wconv_kernel(const float* __restrict__ wh, const float* __restrict__ wu)
{
    const int i = (blockIdx.x * 256 + threadIdx.x) * 4;
    const float* src;
    __half* dst;
    int j = i;
    if (i < CH * CH) { src = wh; dst = g_wh; }
    else             { src = wu; dst = g_wu; j = i - CH * CH; }
    float4 v = *(const float4*)(src + j);
    __half2 h0 = __floats2half2_rn(v.x, v.y);
    __half2 h1 = __floats2half2_rn(v.z, v.w);
    uint2 w;
    w.x = *(unsigned*)&h0;
    w.y = *(unsigned*)&h1;
    *(uint2*)(dst + j) = w;
}

// ---------------------------------------------------------------------------
// 0b) Transpose inputs + fp16 convert: Hand/U [c][n] -> g_ht/g_ut [n][c]
//     For U (which==1), also emit the straight-layout fp16 copy (g_ub).
// ---------------------------------------------------------------------------
__global__ __launch_bounds__(256)
void tin_kernel(const float* __restrict__ Hand, const float* __restrict__ U)
{
    __shared__ float t[32][33];
    const int which = blockIdx.z & 1;
    const int b     = blockIdx.z >> 1;
    const float* src = which ? U : Hand;
    __half* dst = which ? g_ut : g_ht;

    const int n0 = blockIdx.x * 32;
    const int c0 = blockIdx.y * 32;
    const int tx = threadIdx.x & 31;
    const int ty = threadIdx.x >> 5;

    const float* sp = src + (size_t)b * CH * NPIX + (size_t)(c0 + ty) * NPIX + n0 + tx;
    #pragma unroll
    for (int j = 0; j < 4; ++j) {
        const float v = sp[(size_t)j * 8 * NPIX];
        t[ty + j * 8][tx] = v;
        if (which) {
            g_ub[(size_t)b * CH * NPIX + (size_t)(c0 + ty + j * 8) * NPIX + n0 + tx] =
                __float2half(v);
        }
    }
    __syncthreads();

    #pragma unroll
    for (int j = 0; j < 4; ++j) {
        size_t o = (size_t)b * NPIX * CH + (size_t)(n0 + ty + j * 8) * CH + c0 + tx;
        dst[o] = __float2half(t[tx][ty + j * 8]);
    }
}

// ---------------------------------------------------------------------------
// 1) Projection fp16 GEMM: dst[n][o] = Xt[n][:]·W[o][:] + bias[o]
//    Single launch: blockIdx.z = b + BATCH*which. 3-stage pipeline (R8 form).
// ---------------------------------------------------------------------------
__global__ __launch_bounds__(256, 2)
void proj_f16(const float* __restrict__ biasH, const float* __restrict__ biasU)
{
    extern __shared__ char sm_[];
    __half* As = (__half*)sm_;
    __half* Bs = (__half*)(sm_ + 3 * STG_BYTES);

    const int which = blockIdx.z >> 2;
    const int b     = blockIdx.z & 3;
    const __half* xt = which ? g_ut : g_ht;
    const __half* wf = which ? g_wu : g_wh;
    const float* bias = which ? biasU : biasH;
    __half* dst = which ? g_kt : g_qt;

    const int o0 = blockIdx.y * 128;
    const int n0 = blockIdx.x * 128;
    const int tid  = threadIdx.x;
    const int lane = tid & 31;
    const int wid  = tid >> 5;
    const int wm   = (wid >> 2) * 64;   // n
    const int wn   = (wid & 3) * 32;    // o

    const int r  = tid >> 1;
    const int hb = (tid & 1) * 16;
    const __half* ag = xt + (size_t)b * NPIX * CH + (size_t)(n0 + r) * CH + hb;
    const __half* bg = wf + (size_t)(o0 + r) * CH + hb;
    const uint32_t as_ = smem_u32(As) + (uint32_t)(r * 80 + hb * 2);
    const uint32_t bs_ = smem_u32(Bs) + (uint32_t)(r * 80 + hb * 2);

    const uint32_t afrag = smem_u32(As)
        + (uint32_t)(((wm + (lane & 15)) * PW + ((lane >> 4) * 8)) * 2);
    const uint32_t bfrag = smem_u32(Bs)
        + (uint32_t)(((wn + ((lane & 16) >> 1) + (lane & 7)) * PW + (lane & 8)) * 2);

    const int KT = CH / 32;  // 8
    #define PJ_ISSUE(kt) do {                                   \
        const uint32_t so = (uint32_t)((kt) % 3) * STG_BYTES;   \
        cpa16(as_ + so,      ag + (kt) * 32);                   \
        cpa16(as_ + so + 16, ag + (kt) * 32 + 8);               \
        cpa16(bs_ + so,      bg + (kt) * 32);                   \
        cpa16(bs_ + so + 16, bg + (kt) * 32 + 8);               \
        CPA_COMMIT();                                           \
    } while (0)

    PJ_ISSUE(0);
    PJ_ISSUE(1);

    float acc[4][4][4];
    #pragma unroll
    for (int i = 0; i < 4; ++i)
        #pragma unroll
        for (int j = 0; j < 4; ++j)
            #pragma unroll
            for (int q = 0; q < 4; ++q) acc[i][j][q] = 0.f;

    #pragma unroll 1
    for (int kt = 0; kt < KT; ++kt) {
        if (kt + 1 < KT) { CPA_WAIT1(); } else { CPA_WAIT0(); }
        __syncthreads();
        if (kt + 2 < KT) PJ_ISSUE(kt + 2);

        const uint32_t so = (uint32_t)(kt % 3) * STG_BYTES;
        #pragma unroll
        for (int ks = 0; ks < 2; ++ks) {
            unsigned a[4][4], bb[4][2];
            const uint32_t ko = so + (uint32_t)ks * 32;
            #pragma unroll
            for (int mt = 0; mt < 4; ++mt)
                ldsm_x4(a[mt], afrag + ko + (uint32_t)mt * (16 * PW * 2));
            ldsm_x4(&bb[0][0], bfrag + ko);
            ldsm_x4(&bb[2][0], bfrag + ko + (uint32_t)(16 * PW * 2));
            #pragma unroll
            for (int mt = 0; mt < 4; ++mt)
                #pragma unroll
                for (int nt = 0; nt < 4; ++nt)
                    mma_f16(acc[mt][nt], a[mt], bb[nt]);
        }
    }
    #undef PJ_ISSUE

    const int fr = lane >> 2, fc = (lane & 3) * 2;
    __half* db = dst + (size_t)b * NPIX * CH;
    #pragma unroll
    for (int mt = 0; mt < 4; ++mt) {
        const int row = n0 + wm + mt * 16 + fr;
        #pragma unroll
        for (int nt = 0; nt < 4; ++nt) {
            const int col = o0 + wn + nt * 8 + fc;
            const float bv0 = bias[col];
            const float bv1 = bias[col + 1];
            __half2 h0 = __floats2half2_rn(acc[mt][nt][0] + bv0, acc[mt][nt][1] + bv1);
            __half2 h1 = __floats2half2_rn(acc[mt][nt][2] + bv0, acc[mt][nt][3] + bv1);
            *(__half2*)(db + (size_t)row * CH + col)       = h0;
            *(__half2*)(db + (size_t)(row + 8) * CH + col) = h1;
        }
    }
}

// ---------------------------------------------------------------------------
// 2) Logits GEMM fp16 (LDSM fragments) + fused per-tile softmax (ex2.f16x2)
//    3-stage pipeline (R8 form, direct P stores).
// ---------------------------------------------------------------------------
__global__ __launch_bounds__(256, 2)
void sgemm_f16()
{
    extern __shared__ char sm_[];
    __half* Qs = (__half*)sm_;
    __half* Ks = (__half*)(sm_ + 3 * STG_BYTES);
    float*  red = (float*)(sm_ + 6 * STG_BYTES);   // [128][4]

    const int m0 = blockIdx.x * 128;
    const int n0 = blockIdx.y * 128;
    const int b  = blockIdx.z;
    const int tid  = threadIdx.x;
    const int lane = tid & 31;
    const int wid  = tid >> 5;
    const int wm   = (wid >> 2) * 64;
    const int wn   = (wid & 3) * 32;

    const int r  = tid >> 1;
    const int hb = (tid & 1) * 16;
    const __half* qg = g_qt + (size_t)b * NPIX * CH + (size_t)(n0 + r) * CH + hb;
    const __half* kg = g_kt + (size_t)b * NPIX * CH + (size_t)(m0 + r) * CH + hb;
    const uint32_t qs = smem_u32(Qs) + (uint32_t)(r * 80 + hb * 2);
    const uint32_t ks_ = smem_u32(Ks) + (uint32_t)(r * 80 + hb * 2);

    const uint32_t afrag = smem_u32(Qs)
        + (uint32_t)(((wm + (lane & 15)) * PW + ((lane >> 4) * 8)) * 2);
    const uint32_t bfrag = smem_u32(Ks)
        + (uint32_t)(((wn + ((lane & 16) >> 1) + (lane & 7)) * PW + (lane & 8)) * 2);

    const int KT = CH / 32;  // 8 stages
    #define SG_ISSUE(kt) do {                                   \
        const uint32_t so = (uint32_t)((kt) % 3) * STG_BYTES;   \
        cpa16(qs + so,      qg + (kt) * 32);                    \
        cpa16(qs + so + 16, qg + (kt) * 32 + 8);                \
        cpa16(ks_ + so,      kg + (kt) * 32);                   \
        cpa16(ks_ + so + 16, kg + (kt) * 32 + 8);               \
        CPA_COMMIT();                                           \
    } while (0)

    SG_ISSUE(0);
    SG_ISSUE(1);

    float acc[4][4][4];
    #pragma unroll
    for (int i = 0; i < 4; ++i)
        #pragma unroll
        for (int j = 0; j < 4; ++j)
            #pragma unroll
            for (int q = 0; q < 4; ++q) acc[i][j][q] = 0.f;

    #pragma unroll 1
    for (int kt = 0; kt < KT; ++kt) {
        if (kt + 1 < KT) { CPA_WAIT1(); } else { CPA_WAIT0(); }
        __syncthreads();
        if (kt + 2 < KT) SG_ISSUE(kt + 2);

        const uint32_t so = (uint32_t)(kt % 3) * STG_BYTES;
        #pragma unroll
        for (int ks = 0; ks < 2; ++ks) {
            unsigned a[4][4], bb[4][2];
            const uint32_t ko = so + (uint32_t)ks * 32;
            #pragma unroll
            for (int mt = 0; mt < 4; ++mt)
                ldsm_x4(a[mt], afrag + ko + (uint32_t)mt * (16 * PW * 2));
            ldsm_x4(&bb[0][0], bfrag + ko);
            ldsm_x4(&bb[2][0], bfrag + ko + (uint32_t)(16 * PW * 2));
            #pragma unroll
            for (int mt = 0; mt < 4; ++mt)
                #pragma unroll
                for (int nt = 0; nt < 4; ++nt)
                    mma_f16(acc[mt][nt], a[mt], bb[nt]);
        }
    }
    #undef SG_ISSUE

    // ---- fused tile softmax ----
    float rmax[8];
    #pragma unroll
    for (int mt = 0; mt < 4; ++mt)
        #pragma unroll
        for (int h = 0; h < 2; ++h) {
            float v = fmaxf(acc[mt][0][h * 2], acc[mt][0][h * 2 + 1]);
            #pragma unroll
            for (int nt = 1; nt < 4; ++nt)
                v = fmaxf(v, fmaxf(acc[mt][nt][h * 2], acc[mt][nt][h * 2 + 1]));
            rmax[mt * 2 + h] = v;
        }
    #pragma unroll
    for (int s = 0; s < 8; ++s) {
        rmax[s] = fmaxf(rmax[s], __shfl_xor_sync(0xffffffffu, rmax[s], 1));
        rmax[s] = fmaxf(rmax[s], __shfl_xor_sync(0xffffffffu, rmax[s], 2));
    }
    __syncthreads();
    if ((lane & 3) == 0) {
        #pragma unroll
        for (int s = 0; s < 8; ++s) {
            const int rr = wm + (s >> 1) * 16 + (lane >> 2) + (s & 1) * 8;
            red[rr * 4 + (wid & 3)] = rmax[s];
        }
    }
    __syncthreads();
    float tmax[8];
    #pragma unroll
    for (int s = 0; s < 8; ++s) {
        const int rr = wm + (s >> 1) * 16 + (lane >> 2) + (s & 1) * 8;
        tmax[s] = fmaxf(fmaxf(red[rr * 4], red[rr * 4 + 1]),
                        fmaxf(red[rr * 4 + 2], red[rr * 4 + 3]));
    }
    __syncthreads();

    // exp via packed half2 ex2: p = 2^((s - max) * log2e)
    float rsum[8] = {0.f, 0.f, 0.f, 0.f, 0.f, 0.f, 0.f, 0.f};
    #pragma unroll
    for (int mt = 0; mt < 4; ++mt)
        #pragma unroll
        for (int h = 0; h < 2; ++h) {
            const int slot = mt * 2 + h;
            const int rr = wm + mt * 16 + (lane >> 2) + h * 8;
            const float tmL = tmax[slot] * LOG2E;
            __half* pp = g_P + (size_t)b * NPIX * NPIX
                       + (size_t)(n0 + rr) * NPIX + m0 + wn + (lane & 3) * 2;
            #pragma unroll
            for (int nt = 0; nt < 4; ++nt) {
                const float t0 = fmaf(acc[mt][nt][h * 2],     LOG2E, -tmL);
                const float t1 = fmaf(acc[mt][nt][h * 2 + 1], LOG2E, -tmL);
                __half2 th = __floats2half2_rn(t0, t1);
                unsigned pu;
                asm("ex2.approx.f16x2 %0, %1;" : "=r"(pu) : "r"(*(unsigned*)&th));
                __half2 ph = *(__half2*)&pu;
                float2 pf = __half22float2(ph);
                rsum[slot] += pf.x + pf.y;
                *(__half2*)(pp + nt * 8) = ph;
            }
        }
    #pragma unroll
    for (int s = 0; s < 8; ++s) {
        rsum[s] += __shfl_xor_sync(0xffffffffu, rsum[s], 1);
        rsum[s] += __shfl_xor_sync(0xffffffffu, rsum[s], 2);
    }
    if ((lane & 3) == 0) {
        #pragma unroll
        for (int s = 0; s < 8; ++s) {
            const int rr = wm + (s >> 1) * 16 + (lane >> 2) + (s & 1) * 8;
            red[rr * 4 + (wid & 3)] = rsum[s];
        }
    }
    __syncthreads();
    if ((wid & 3) == 0 && (lane & 3) == 0) {
        #pragma unroll
        for (int s = 0; s < 8; ++s) {
            const int rr = wm + (s >> 1) * 16 + (lane >> 2) + (s & 1) * 8;
            const float tot = red[rr * 4] + red[rr * 4 + 1] + red[rr * 4 + 2] + red[rr * 4 + 3];
            const int gi = (b * NPIX + n0 + rr) * 32 + blockIdx.x;
            g_pmx[gi]  = tmax[s];
            g_psum[gi] = tot;
        }
    }
}

// ---------------------------------------------------------------------------
// 3) AV GEMM fp16 (LDSM fragments). 3-stage pipeline.
//    Combine folded into prologue: scales computed per-CTA into smem.
// ---------------------------------------------------------------------------
__global__ __launch_bounds__(256, 2)
void av_f16(float* __restrict__ out)
{
    extern __shared__ char sm_[];
    __half* Us = (__half*)sm_;
    __half* Ps = (__half*)(sm_ + 3 * STG_BYTES);
    float*  scs = (float*)(sm_ + 6 * STG_BYTES);   // [128][32] scales

    const int n0 = blockIdx.x * 128;
    const int c0 = blockIdx.y * 128;
    const int b  = blockIdx.z;
    const int tid  = threadIdx.x;
    const int lane = tid & 31;
    const int wid  = tid >> 5;
    const int wm   = (wid >> 2) * 64;
    const int wn   = (wid & 3) * 32;

    const int r  = tid >> 1;
    const int hb = (tid & 1) * 16;
    const __half* ug = g_ub + (size_t)b * CH * NPIX   + (size_t)(c0 + r) * NPIX + hb;
    const __half* pg = g_P  + (size_t)b * NPIX * NPIX + (size_t)(n0 + r) * NPIX + hb;
    const uint32_t us = smem_u32(Us) + (uint32_t)(r * 80 + hb * 2);
    const uint32_t ps = smem_u32(Ps) + (uint32_t)(r * 80 + hb * 2);

    const uint32_t afrag = smem_u32(Us)
        + (uint32_t)(((wm + (lane & 15)) * PW + ((lane >> 4) * 8)) * 2);
    const uint32_t bfrag = smem_u32(Ps)
        + (uint32_t)(((wn + ((lane & 16) >> 1) + (lane & 7)) * PW + (lane & 8)) * 2);

    const int KT = NPIX / 32;  // 128 stages
    #define AV_ISSUE(kt) do {                                   \
        const uint32_t so = (uint32_t)((kt) % 3) * STG_BYTES;   \
        cpa16(us + so,      ug + (kt) * 32);                    \
        cpa16(us + so + 16, ug + (kt) * 32 + 8);                \
        cpa16(ps + so,      pg + (kt) * 32);                    \
        cpa16(ps + so + 16, pg + (kt) * 32 + 8);                \
        CPA_COMMIT();                                           \
    } while (0)

    AV_ISSUE(0);
    AV_ISSUE(1);

    // inline combine: per-row scale factors for this CTA's n-range
    // (exact arithmetic of the old combine_kernel, lane = m-tile)
    #pragma unroll 1
    for (int i = 0; i < 16; ++i) {
        const int row = wid * 16 + i;
        const int gi = (b * NPIX + n0 + row) * 32 + lane;
        const float mx = g_pmx[gi];
        const float sm = g_psum[gi];
        const float M  = warpMax(mx);
        const float e  = __expf(mx - M);
        const float tot = warpSum(sm * e);
        scs[row * 32 + lane] = e / tot;
    }
    __syncthreads();

    float acc[4][4][4];
    #pragma unroll
    for (int i = 0; i < 4; ++i)
        #pragma unroll
        for (int j = 0; j < 4; ++j)
            #pragma unroll
            for (int q = 0; q < 4; ++q) acc[i][j][q] = 0.f;

    __half2 sc[4];

    #pragma unroll 1
    for (int kt = 0; kt < KT; ++kt) {
        if ((kt & 3) == 0) {
            #pragma unroll
            for (int nt = 0; nt < 4; ++nt) {
                const int n = wn + nt * 8 + (lane >> 2);
                sc[nt] = __float2half2_rn(scs[n * 32 + (kt >> 2)]);
            }
        }
        if (kt + 1 < KT) { CPA_WAIT1(); } else { CPA_WAIT0(); }
        __syncthreads();
        if (kt + 2 < KT) AV_ISSUE(kt + 2);

        const uint32_t so = (uint32_t)(kt % 3) * STG_BYTES;
        #pragma unroll
        for (int ks = 0; ks < 2; ++ks) {
            unsigned a[4][4], bb[4][2];
            const uint32_t ko = so + (uint32_t)ks * 32;
            #pragma unroll
            for (int mt = 0; mt < 4; ++mt)
                ldsm_x4(a[mt], afrag + ko + (uint32_t)mt * (16 * PW * 2));
            ldsm_x4(&bb[0][0], bfrag + ko);
            ldsm_x4(&bb[2][0], bfrag + ko + (uint32_t)(16 * PW * 2));
            #pragma unroll
            for (int nt = 0; nt < 4; ++nt) {
                __half2 b0 = __hmul2(*(__half2*)&bb[nt][0], sc[nt]);
                __half2 b1 = __hmul2(*(__half2*)&bb[nt][1], sc[nt]);
                bb[nt][0] = *(unsigned*)&b0;
                bb[nt][1] = *(unsigned*)&b1;
            }
            #pragma unroll
            for (int mt = 0; mt < 4; ++mt)
                #pragma unroll
                for (int nt = 0; nt < 4; ++nt)
                    mma_f16(acc[mt][nt], a[mt], bb[nt]);
        }
    }
    #undef AV_ISSUE

    const int fr = lane >> 2, fc = (lane & 3) * 2;
    #pragma unroll
    for (int mt = 0; mt < 4; ++mt) {
        const int row = c0 + wm + mt * 16 + fr;
        #pragma unroll
        for (int nt = 0; nt < 4; ++nt) {
            const int col = n0 + wn + nt * 8 + fc;
            float* p0 = out + (size_t)b * CH * NPIX + (size_t)row * NPIX + col;
            float* p1 = p0 + (size_t)8 * NPIX;
            *(float2*)p0 = make_float2(acc[mt][nt][0], acc[mt][nt][1]);
            *(float2*)p1 = make_float2(acc[mt][nt][2], acc[mt][nt][3]);
        }
    }
}

// ---------------------------------------------------------------------------
// 4) GroupNorm(+residual) in place on d_out — 1024 threads/block
// ---------------------------------------------------------------------------
__global__ __launch_bounds__(1024)
void gn_kernel(float* __restrict__ out, const float* __restrict__ Hand,
               const float* __restrict__ gw, const float* __restrict__ gb)
{
    const int b = blockIdx.x >> 5;
    const int g = blockIdx.x & 31;
    const size_t off = (size_t)b * CH * NPIX + (size_t)g * CPG * NPIX;
    float* base = out + off;
    const float* hb = Hand + off;
    const int tid = threadIdx.x;

    float s1 = 0.f, s2 = 0.f;
    #pragma unroll
    for (int i = 0; i < 8; ++i) {
        float4 v = *(const float4*)(base + i * 4096 + tid * 4);
        s1 += v.x + v.y + v.z + v.w;
        s2 += v.x * v.x + v.y * v.y + v.z * v.z + v.w * v.w;
    }
    s1 = warpSum(s1);
    s2 = warpSum(s2);
    __shared__ float a1[32], a2[32];
    if ((tid & 31) == 0) { a1[tid >> 5] = s1; a2[tid >> 5] = s2; }
    __syncthreads();
    __shared__ float mean_s, rstd_s;
    if (tid < 32) {
        float S1 = a1[tid], S2 = a2[tid];
        S1 = warpSum(S1);
        S2 = warpSum(S2);
        if (tid == 0) {
            const float inv  = 1.f / (float)(CPG * NPIX);
            const float mean = S1 * inv;
            const float var  = S2 * inv - mean * mean;
            mean_s = mean;
            rstd_s = rsqrtf(var + 1e-5f);
        }
    }
    __syncthreads();
    const float mean = mean_s, rstd = rstd_s;

    #pragma unroll
    for (int i = 0; i < 8; ++i) {
        const int f = i * 4096 + tid * 4;
        const int c = g * CPG + (f >> 12);
        const float w  = gw[c];
        const float bi = gb[c];
        float4 v = *(const float4*)(base + f);
        float4 h = *(const float4*)(hb + f);
        v.x = (v.x - mean) * rstd * w + bi + h.x;
        v.y = (v.y - mean) * rstd * w + bi + h.y;
        v.z = (v.z - mean) * rstd * w + bi + h.z;
        v.w = (v.w - mean) * rstd * w + bi + h.w;
        *(float4*)(base + f) = v;
    }
}

// ---------------------------------------------------------------------------
extern "C" void kernel_launch(void* const* d_in, const int* in_sizes, int n_in,
                              void* d_out, int out_size)
{
    const float* Hand = (const float*)d_in[0];
    const float* U    = (const float*)d_in[1];
    const float* WHw  = (const float*)d_in[2];
    const float* WHb  = (const float*)d_in[3];
    const float* WUw  = (const float*)d_in[4];
    const float* WUb  = (const float*)d_in[5];
    const float* gnw  = (const float*)d_in[6];
    const float* gnb  = (const float*)d_in[7];
    float* out = (float*)d_out;

    const int pj_smem = 6 * STG_BYTES;                      // 61440
    const int sg_smem = 6 * STG_BYTES + 128 * 4 * 4;        // 63488
    const int av_smem = 6 * STG_BYTES + 128 * 32 * 4;       // 77824
    cudaFuncSetAttribute(proj_f16,  cudaFuncAttributeMaxDynamicSharedMemorySize, pj_smem);
    cudaFuncSetAttribute(sgemm_f16, cudaFuncAttributeMaxDynamicSharedMemorySize, sg_smem);
    cudaFuncSetAttribute(av_f16,    cudaFuncAttributeMaxDynamicSharedMemorySize, av_smem);

    wconv_kernel<<<(2 * CH * CH) / (256 * 4), 256>>>(WHw, WUw);

    dim3 tg(NPIX / 32, CH / 32, BATCH * 2);
    tin_kernel<<<tg, 256>>>(Hand, U);

    dim3 pg(NPIX / 128, CH / 128, BATCH * 2);
    proj_f16<<<pg, 256, pj_smem>>>(WHb, WUb);

    dim3 sg(NPIX / 128, NPIX / 128, BATCH);
    sgemm_f16<<<sg, 256, sg_smem>>>();

    dim3 ag(NPIX / 128, CH / 128, BATCH);
    av_f16<<<ag, 256, av_smem>>>(out);

    gn_kernel<<<BATCH * NGRP, 1024>>>(out, Hand, gnw, gnb);
}

// round 16
// speedup vs baseline: 1.0514x; 1.0188x over previous
#include <cuda_runtime.h>
#include <cuda_fp16.h>
#include <cstdint>

#define BATCH 4
#define CH    256
#define NPIX  4096
#define NGRP  32
#define CPG   8

// ---------------------------------------------------------------------------
// Scratch (device globals)
// ---------------------------------------------------------------------------
__device__ __half g_ht[BATCH * NPIX * CH];           // Hand^T fp16 [b][n][c]
__device__ __half g_ut[BATCH * NPIX * CH];           // U^T    fp16 [b][n][c]
__device__ __half g_wh[CH * CH];                     // WH fp16 [o][c]
__device__ __half g_wu[CH * CH];                     // WU fp16 [o][c]
__device__ __half g_qt[BATCH * NPIX * CH];           // q^T fp16 [b][n][c]
__device__ __half g_kt[BATCH * NPIX * CH];           // k^T fp16 [b][m][c]
__device__ __half g_ub[BATCH * CH * NPIX];           // U fp16   [b][c][m]
__device__ __half g_P [(size_t)BATCH * NPIX * NPIX]; // exp(s - mx_tile) fp16
__device__ float  g_pmx  [BATCH * NPIX * 32];
__device__ float  g_psum [BATCH * NPIX * 32];

// ---------------------------------------------------------------------------
// Helpers
// ---------------------------------------------------------------------------
__device__ __forceinline__ float warpMax(float v) {
    #pragma unroll
    for (int o = 16; o > 0; o >>= 1)
        v = fmaxf(v, __shfl_xor_sync(0xffffffffu, v, o));
    return v;
}
__device__ __forceinline__ float warpSum(float v) {
    #pragma unroll
    for (int o = 16; o > 0; o >>= 1)
        v += __shfl_xor_sync(0xffffffffu, v, o);
    return v;
}
// fp16 m16n8k16, fp32 accumulate
__device__ __forceinline__ void mma_f16(float* c, const unsigned* a, const unsigned* b) {
    asm volatile(
        "mma.sync.aligned.m16n8k16.row.col.f32.f16.f16.f32 "
        "{%0,%1,%2,%3},{%4,%5,%6,%7},{%8,%9},{%0,%1,%2,%3};"
        : "+f"(c[0]), "+f"(c[1]), "+f"(c[2]), "+f"(c[3])
        : "r"(a[0]), "r"(a[1]), "r"(a[2]), "r"(a[3]), "r"(b[0]), "r"(b[1]));
}
__device__ __forceinline__ void ldsm_x4(unsigned* r, uint32_t addr) {
    asm volatile("ldmatrix.sync.aligned.m8n8.x4.shared.b16 {%0,%1,%2,%3}, [%4];"
                 : "=r"(r[0]), "=r"(r[1]), "=r"(r[2]), "=r"(r[3]) : "r"(addr));
}
__device__ __forceinline__ uint32_t smem_u32(const void* p) {
    uint32_t a;
    asm("{ .reg .u64 t; cvta.to.shared.u64 t, %1; cvt.u32.u64 %0, t; }" : "=r"(a) : "l"(p));
    return a;
}
__device__ __forceinline__ void cpa16(uint32_t dst, const void* src) {
    asm volatile("cp.async.cg.shared.global [%0], [%1], 16;" :: "r"(dst), "l"(src));
}
#define CPA_COMMIT() asm volatile("cp.async.commit_group;" ::: "memory")
#define CPA_WAIT1()  asm volatile("cp.async.wait_group 1;" ::: "memory")
#define CPA_WAIT0()  asm volatile("cp.async.wait_group 0;" ::: "memory")

#define PW        40
#define STG_BYTES (128 * PW * 2)   // 10240 B per 128-row stage
#define LOG2E     1.4426950408889634f

// ---------------------------------------------------------------------------
// 0a) Weights fp32 -> fp16
// ---------------------------------------------------------------------------
__global__ __launch_bounds__(256)
void wconv_kernel(const float* __restrict__ wh, const float* __restrict__ wu)
{
    const int i = (blockIdx.x * 256 + threadIdx.x) * 4;
    const float* src;
    __half* dst;
    int j = i;
    if (i < CH * CH) { src = wh; dst = g_wh; }
    else             { src = wu; dst = g_wu; j = i - CH * CH; }
    float4 v = *(const float4*)(src + j);
    __half2 h0 = __floats2half2_rn(v.x, v.y);
    __half2 h1 = __floats2half2_rn(v.z, v.w);
    uint2 w;
    w.x = *(unsigned*)&h0;
    w.y = *(unsigned*)&h1;
    *(uint2*)(dst + j) = w;
}

// ---------------------------------------------------------------------------
// 0b) Transpose inputs + fp16 convert: Hand/U [c][n] -> g_ht/g_ut [n][c]
//     For U (which==1), also emit the straight-layout fp16 copy (g_ub).
// ---------------------------------------------------------------------------
__global__ __launch_bounds__(256)
void tin_kernel(const float* __restrict__ Hand, const float* __restrict__ U)
{
    __shared__ float t[32][33];
    const int which = blockIdx.z & 1;
    const int b     = blockIdx.z >> 1;
    const float* src = which ? U : Hand;
    __half* dst = which ? g_ut : g_ht;

    const int n0 = blockIdx.x * 32;
    const int c0 = blockIdx.y * 32;
    const int tx = threadIdx.x & 31;
    const int ty = threadIdx.x >> 5;

    const float* sp = src + (size_t)b * CH * NPIX + (size_t)(c0 + ty) * NPIX + n0 + tx;
    #pragma unroll
    for (int j = 0; j < 4; ++j) {
        const float v = sp[(size_t)j * 8 * NPIX];
        t[ty + j * 8][tx] = v;
        if (which) {
            g_ub[(size_t)b * CH * NPIX + (size_t)(c0 + ty + j * 8) * NPIX + n0 + tx] =
                __float2half(v);
        }
    }
    __syncthreads();

    #pragma unroll
    for (int j = 0; j < 4; ++j) {
        size_t o = (size_t)b * NPIX * CH + (size_t)(n0 + ty + j * 8) * CH + c0 + tx;
        dst[o] = __float2half(t[tx][ty + j * 8]);
    }
}

// ---------------------------------------------------------------------------
// 1) Projection fp16 GEMM: dst[n][o] = Xt[n][:]·W[o][:] + bias[o]
//    Single launch: blockIdx.z = b + BATCH*which. 3-stage pipeline.
// ---------------------------------------------------------------------------
__global__ __launch_bounds__(256, 2)
void proj_f16(const float* __restrict__ biasH, const float* __restrict__ biasU)
{
    extern __shared__ char sm_[];
    __half* As = (__half*)sm_;
    __half* Bs = (__half*)(sm_ + 3 * STG_BYTES);

    const int which = blockIdx.z >> 2;
    const int b     = blockIdx.z & 3;
    const __half* xt = which ? g_ut : g_ht;
    const __half* wf = which ? g_wu : g_wh;
    const float* bias = which ? biasU : biasH;
    __half* dst = which ? g_kt : g_qt;

    const int o0 = blockIdx.y * 128;
    const int n0 = blockIdx.x * 128;
    const int tid  = threadIdx.x;
    const int lane = tid & 31;
    const int wid  = tid >> 5;
    const int wm   = (wid >> 2) * 64;   // n
    const int wn   = (wid & 3) * 32;    // o

    const int r  = tid >> 1;
    const int hb = (tid & 1) * 16;
    const __half* ag = xt + (size_t)b * NPIX * CH + (size_t)(n0 + r) * CH + hb;
    const __half* bg = wf + (size_t)(o0 + r) * CH + hb;
    const uint32_t as_ = smem_u32(As) + (uint32_t)(r * 80 + hb * 2);
    const uint32_t bs_ = smem_u32(Bs) + (uint32_t)(r * 80 + hb * 2);

    const uint32_t afrag = smem_u32(As)
        + (uint32_t)(((wm + (lane & 15)) * PW + ((lane >> 4) * 8)) * 2);
    const uint32_t bfrag = smem_u32(Bs)
        + (uint32_t)(((wn + ((lane & 16) >> 1) + (lane & 7)) * PW + (lane & 8)) * 2);

    const int KT = CH / 32;  // 8
    #define PJ_ISSUE(kt) do {                                   \
        const uint32_t so = (uint32_t)((kt) % 3) * STG_BYTES;   \
        cpa16(as_ + so,      ag + (kt) * 32);                   \
        cpa16(as_ + so + 16, ag + (kt) * 32 + 8);               \
        cpa16(bs_ + so,      bg + (kt) * 32);                   \
        cpa16(bs_ + so + 16, bg + (kt) * 32 + 8);               \
        CPA_COMMIT();                                           \
    } while (0)

    PJ_ISSUE(0);
    PJ_ISSUE(1);

    float acc[4][4][4];
    #pragma unroll
    for (int i = 0; i < 4; ++i)
        #pragma unroll
        for (int j = 0; j < 4; ++j)
            #pragma unroll
            for (int q = 0; q < 4; ++q) acc[i][j][q] = 0.f;

    #pragma unroll 1
    for (int kt = 0; kt < KT; ++kt) {
        if (kt + 1 < KT) { CPA_WAIT1(); } else { CPA_WAIT0(); }
        __syncthreads();
        if (kt + 2 < KT) PJ_ISSUE(kt + 2);

        const uint32_t so = (uint32_t)(kt % 3) * STG_BYTES;
        #pragma unroll
        for (int ks = 0; ks < 2; ++ks) {
            unsigned a[4][4], bb[4][2];
            const uint32_t ko = so + (uint32_t)ks * 32;
            #pragma unroll
            for (int mt = 0; mt < 4; ++mt)
                ldsm_x4(a[mt], afrag + ko + (uint32_t)mt * (16 * PW * 2));
            ldsm_x4(&bb[0][0], bfrag + ko);
            ldsm_x4(&bb[2][0], bfrag + ko + (uint32_t)(16 * PW * 2));
            #pragma unroll
            for (int mt = 0; mt < 4; ++mt)
                #pragma unroll
                for (int nt = 0; nt < 4; ++nt)
                    mma_f16(acc[mt][nt], a[mt], bb[nt]);
        }
    }
    #undef PJ_ISSUE

    const int fr = lane >> 2, fc = (lane & 3) * 2;
    __half* db = dst + (size_t)b * NPIX * CH;
    #pragma unroll
    for (int mt = 0; mt < 4; ++mt) {
        const int row = n0 + wm + mt * 16 + fr;
        #pragma unroll
        for (int nt = 0; nt < 4; ++nt) {
            const int col = o0 + wn + nt * 8 + fc;
            const float bv0 = bias[col];
            const float bv1 = bias[col + 1];
            __half2 h0 = __floats2half2_rn(acc[mt][nt][0] + bv0, acc[mt][nt][1] + bv1);
            __half2 h1 = __floats2half2_rn(acc[mt][nt][2] + bv0, acc[mt][nt][3] + bv1);
            *(__half2*)(db + (size_t)row * CH + col)       = h0;
            *(__half2*)(db + (size_t)(row + 8) * CH + col) = h1;
        }
    }
}

// ---------------------------------------------------------------------------
// 2) Logits GEMM fp16 (LDSM fragments) + fused per-tile softmax (ex2.f16x2)
//    3-stage pipeline (R15 form).
// ---------------------------------------------------------------------------
__global__ __launch_bounds__(256, 2)
void sgemm_f16()
{
    extern __shared__ char sm_[];
    __half* Qs = (__half*)sm_;
    __half* Ks = (__half*)(sm_ + 3 * STG_BYTES);
    float*  red = (float*)(sm_ + 6 * STG_BYTES);   // [128][4]

    const int m0 = blockIdx.x * 128;
    const int n0 = blockIdx.y * 128;
    const int b  = blockIdx.z;
    const int tid  = threadIdx.x;
    const int lane = tid & 31;
    const int wid  = tid >> 5;
    const int wm   = (wid >> 2) * 64;
    const int wn   = (wid & 3) * 32;

    const int r  = tid >> 1;
    const int hb = (tid & 1) * 16;
    const __half* qg = g_qt + (size_t)b * NPIX * CH + (size_t)(n0 + r) * CH + hb;
    const __half* kg = g_kt + (size_t)b * NPIX * CH + (size_t)(m0 + r) * CH + hb;
    const uint32_t qs = smem_u32(Qs) + (uint32_t)(r * 80 + hb * 2);
    const uint32_t ks_ = smem_u32(Ks) + (uint32_t)(r * 80 + hb * 2);

    const uint32_t afrag = smem_u32(Qs)
        + (uint32_t)(((wm + (lane & 15)) * PW + ((lane >> 4) * 8)) * 2);
    const uint32_t bfrag = smem_u32(Ks)
        + (uint32_t)(((wn + ((lane & 16) >> 1) + (lane & 7)) * PW + (lane & 8)) * 2);

    const int KT = CH / 32;  // 8 stages
    #define SG_ISSUE(kt) do {                                   \
        const uint32_t so = (uint32_t)((kt) % 3) * STG_BYTES;   \
        cpa16(qs + so,      qg + (kt) * 32);                    \
        cpa16(qs + so + 16, qg + (kt) * 32 + 8);                \
        cpa16(ks_ + so,      kg + (kt) * 32);                   \
        cpa16(ks_ + so + 16, kg + (kt) * 32 + 8);               \
        CPA_COMMIT();                                           \
    } while (0)

    SG_ISSUE(0);
    SG_ISSUE(1);

    float acc[4][4][4];
    #pragma unroll
    for (int i = 0; i < 4; ++i)
        #pragma unroll
        for (int j = 0; j < 4; ++j)
            #pragma unroll
            for (int q = 0; q < 4; ++q) acc[i][j][q] = 0.f;

    #pragma unroll 1
    for (int kt = 0; kt < KT; ++kt) {
        if (kt + 1 < KT) { CPA_WAIT1(); } else { CPA_WAIT0(); }
        __syncthreads();
        if (kt + 2 < KT) SG_ISSUE(kt + 2);

        const uint32_t so = (uint32_t)(kt % 3) * STG_BYTES;
        #pragma unroll
        for (int ks = 0; ks < 2; ++ks) {
            unsigned a[4][4], bb[4][2];
            const uint32_t ko = so + (uint32_t)ks * 32;
            #pragma unroll
            for (int mt = 0; mt < 4; ++mt)
                ldsm_x4(a[mt], afrag + ko + (uint32_t)mt * (16 * PW * 2));
            ldsm_x4(&bb[0][0], bfrag + ko);
            ldsm_x4(&bb[2][0], bfrag + ko + (uint32_t)(16 * PW * 2));
            #pragma unroll
            for (int mt = 0; mt < 4; ++mt)
                #pragma unroll
                for (int nt = 0; nt < 4; ++nt)
                    mma_f16(acc[mt][nt], a[mt], bb[nt]);
        }
    }
    #undef SG_ISSUE

    // ---- fused tile softmax ----
    float rmax[8];
    #pragma unroll
    for (int mt = 0; mt < 4; ++mt)
        #pragma unroll
        for (int h = 0; h < 2; ++h) {
            float v = fmaxf(acc[mt][0][h * 2], acc[mt][0][h * 2 + 1]);
            #pragma unroll
            for (int nt = 1; nt < 4; ++nt)
                v = fmaxf(v, fmaxf(acc[mt][nt][h * 2], acc[mt][nt][h * 2 + 1]));
            rmax[mt * 2 + h] = v;
        }
    #pragma unroll
    for (int s = 0; s < 8; ++s) {
        rmax[s] = fmaxf(rmax[s], __shfl_xor_sync(0xffffffffu, rmax[s], 1));
        rmax[s] = fmaxf(rmax[s], __shfl_xor_sync(0xffffffffu, rmax[s], 2));
    }
    __syncthreads();
    if ((lane & 3) == 0) {
        #pragma unroll
        for (int s = 0; s < 8; ++s) {
            const int rr = wm + (s >> 1) * 16 + (lane >> 2) + (s & 1) * 8;
            red[rr * 4 + (wid & 3)] = rmax[s];
        }
    }
    __syncthreads();
    float tmax[8];
    #pragma unroll
    for (int s = 0; s < 8; ++s) {
        const int rr = wm + (s >> 1) * 16 + (lane >> 2) + (s & 1) * 8;
        tmax[s] = fmaxf(fmaxf(red[rr * 4], red[rr * 4 + 1]),
                        fmaxf(red[rr * 4 + 2], red[rr * 4 + 3]));
    }
    __syncthreads();

    // exp via packed half2 ex2: p = 2^((s - max) * log2e)
    float rsum[8] = {0.f, 0.f, 0.f, 0.f, 0.f, 0.f, 0.f, 0.f};
    #pragma unroll
    for (int mt = 0; mt < 4; ++mt)
        #pragma unroll
        for (int h = 0; h < 2; ++h) {
            const int slot = mt * 2 + h;
            const int rr = wm + mt * 16 + (lane >> 2) + h * 8;
            const float tmL = tmax[slot] * LOG2E;
            __half* pp = g_P + (size_t)b * NPIX * NPIX
                       + (size_t)(n0 + rr) * NPIX + m0 + wn + (lane & 3) * 2;
            #pragma unroll
            for (int nt = 0; nt < 4; ++nt) {
                const float t0 = fmaf(acc[mt][nt][h * 2],     LOG2E, -tmL);
                const float t1 = fmaf(acc[mt][nt][h * 2 + 1], LOG2E, -tmL);
                __half2 th = __floats2half2_rn(t0, t1);
                unsigned pu;
                asm("ex2.approx.f16x2 %0, %1;" : "=r"(pu) : "r"(*(unsigned*)&th));
                __half2 ph = *(__half2*)&pu;
                float2 pf = __half22float2(ph);
                rsum[slot] += pf.x + pf.y;
                *(__half2*)(pp + nt * 8) = ph;
            }
        }
    #pragma unroll
    for (int s = 0; s < 8; ++s) {
        rsum[s] += __shfl_xor_sync(0xffffffffu, rsum[s], 1);
        rsum[s] += __shfl_xor_sync(0xffffffffu, rsum[s], 2);
    }
    if ((lane & 3) == 0) {
        #pragma unroll
        for (int s = 0; s < 8; ++s) {
            const int rr = wm + (s >> 1) * 16 + (lane >> 2) + (s & 1) * 8;
            red[rr * 4 + (wid & 3)] = rsum[s];
        }
    }
    __syncthreads();
    if ((wid & 3) == 0 && (lane & 3) == 0) {
        #pragma unroll
        for (int s = 0; s < 8; ++s) {
            const int rr = wm + (s >> 1) * 16 + (lane >> 2) + (s & 1) * 8;
            const float tot = red[rr * 4] + red[rr * 4 + 1] + red[rr * 4 + 2] + red[rr * 4 + 3];
            const int gi = (b * NPIX + n0 + rr) * 32 + blockIdx.x;
            g_pmx[gi]  = tmax[s];
            g_psum[gi] = tot;
        }
    }
}

// ---------------------------------------------------------------------------
// 3) AV GEMM fp16 (LDSM fragments). 3-stage pipeline.
//    Combine folded into prologue: batched loads + interleaved shuffle chains.
// ---------------------------------------------------------------------------
__global__ __launch_bounds__(256, 2)
void av_f16(float* __restrict__ out)
{
    extern __shared__ char sm_[];
    __half* Us = (__half*)sm_;
    __half* Ps = (__half*)(sm_ + 3 * STG_BYTES);
    float*  scs = (float*)(sm_ + 6 * STG_BYTES);   // [128][32] scales

    const int n0 = blockIdx.x * 128;
    const int c0 = blockIdx.y * 128;
    const int b  = blockIdx.z;
    const int tid  = threadIdx.x;
    const int lane = tid & 31;
    const int wid  = tid >> 5;
    const int wm   = (wid >> 2) * 64;
    const int wn   = (wid & 3) * 32;

    const int r  = tid >> 1;
    const int hb = (tid & 1) * 16;
    const __half* ug = g_ub + (size_t)b * CH * NPIX   + (size_t)(c0 + r) * NPIX + hb;
    const __half* pg = g_P  + (size_t)b * NPIX * NPIX + (size_t)(n0 + r) * NPIX + hb;
    const uint32_t us = smem_u32(Us) + (uint32_t)(r * 80 + hb * 2);
    const uint32_t ps = smem_u32(Ps) + (uint32_t)(r * 80 + hb * 2);

    const uint32_t afrag = smem_u32(Us)
        + (uint32_t)(((wm + (lane & 15)) * PW + ((lane >> 4) * 8)) * 2);
    const uint32_t bfrag = smem_u32(Ps)
        + (uint32_t)(((wn + ((lane & 16) >> 1) + (lane & 7)) * PW + (lane & 8)) * 2);

    const int KT = NPIX / 32;  // 128 stages
    #define AV_ISSUE(kt) do {                                   \
        const uint32_t so = (uint32_t)((kt) % 3) * STG_BYTES;   \
        cpa16(us + so,      ug + (kt) * 32);                    \
        cpa16(us + so + 16, ug + (kt) * 32 + 8);                \
        cpa16(ps + so,      pg + (kt) * 32);                    \
        cpa16(ps + so + 16, pg + (kt) * 32 + 8);                \
        CPA_COMMIT();                                           \
    } while (0)

    AV_ISSUE(0);
    AV_ISSUE(1);

    // inline combine (exact arithmetic of old combine_kernel) — batched:
    // all loads in flight first, then 8 interleaved shuffle chains per group.
    #pragma unroll
    for (int g = 0; g < 2; ++g) {
        float mx[8], sm[8];
        #pragma unroll
        for (int i = 0; i < 8; ++i) {
            const int row = wid * 16 + g * 8 + i;
            const int gi = (b * NPIX + n0 + row) * 32 + lane;
            mx[i] = g_pmx[gi];
            sm[i] = g_psum[gi];
        }
        float M[8];
        #pragma unroll
        for (int i = 0; i < 8; ++i) M[i] = mx[i];
        #pragma unroll
        for (int o = 16; o > 0; o >>= 1)
            #pragma unroll
            for (int i = 0; i < 8; ++i)
                M[i] = fmaxf(M[i], __shfl_xor_sync(0xffffffffu, M[i], o));
        float e[8], tot[8];
        #pragma unroll
        for (int i = 0; i < 8; ++i) {
            e[i]   = __expf(mx[i] - M[i]);
            tot[i] = sm[i] * e[i];
        }
        #pragma unroll
        for (int o = 16; o > 0; o >>= 1)
            #pragma unroll
            for (int i = 0; i < 8; ++i)
                tot[i] += __shfl_xor_sync(0xffffffffu, tot[i], o);
        #pragma unroll
        for (int i = 0; i < 8; ++i) {
            const int row = wid * 16 + g * 8 + i;
            scs[row * 32 + lane] = e[i] / tot[i];
        }
    }
    __syncthreads();

    float acc[4][4][4];
    #pragma unroll
    for (int i = 0; i < 4; ++i)
        #pragma unroll
        for (int j = 0; j < 4; ++j)
            #pragma unroll
            for (int q = 0; q < 4; ++q) acc[i][j][q] = 0.f;

    __half2 sc[4];

    #pragma unroll 1
    for (int kt = 0; kt < KT; ++kt) {
        if ((kt & 3) == 0) {
            #pragma unroll
            for (int nt = 0; nt < 4; ++nt) {
                const int n = wn + nt * 8 + (lane >> 2);
                sc[nt] = __float2half2_rn(scs[n * 32 + (kt >> 2)]);
            }
        }
        if (kt + 1 < KT) { CPA_WAIT1(); } else { CPA_WAIT0(); }
        __syncthreads();
        if (kt + 2 < KT) AV_ISSUE(kt + 2);

        const uint32_t so = (uint32_t)(kt % 3) * STG_BYTES;
        #pragma unroll
        for (int ks = 0; ks < 2; ++ks) {
            unsigned a[4][4], bb[4][2];
            const uint32_t ko = so + (uint32_t)ks * 32;
            #pragma unroll
            for (int mt = 0; mt < 4; ++mt)
                ldsm_x4(a[mt], afrag + ko + (uint32_t)mt * (16 * PW * 2));
            ldsm_x4(&bb[0][0], bfrag + ko);
            ldsm_x4(&bb[2][0], bfrag + ko + (uint32_t)(16 * PW * 2));
            #pragma unroll
            for (int nt = 0; nt < 4; ++nt) {
                __half2 b0 = __hmul2(*(__half2*)&bb[nt][0], sc[nt]);
                __half2 b1 = __hmul2(*(__half2*)&bb[nt][1], sc[nt]);
                bb[nt][0] = *(unsigned*)&b0;
                bb[nt][1] = *(unsigned*)&b1;
            }
            #pragma unroll
            for (int mt = 0; mt < 4; ++mt)
                #pragma unroll
                for (int nt = 0; nt < 4; ++nt)
                    mma_f16(acc[mt][nt], a[mt], bb[nt]);
        }
    }
    #undef AV_ISSUE

    const int fr = lane >> 2, fc = (lane & 3) * 2;
    #pragma unroll
    for (int mt = 0; mt < 4; ++mt) {
        const int row = c0 + wm + mt * 16 + fr;
        #pragma unroll
        for (int nt = 0; nt < 4; ++nt) {
            const int col = n0 + wn + nt * 8 + fc;
            float* p0 = out + (size_t)b * CH * NPIX + (size_t)row * NPIX + col;
            float* p1 = p0 + (size_t)8 * NPIX;
            *(float2*)p0 = make_float2(acc[mt][nt][0], acc[mt][nt][1]);
            *(float2*)p1 = make_float2(acc[mt][nt][2], acc[mt][nt][3]);
        }
    }
}

// ---------------------------------------------------------------------------
// 4) GroupNorm(+residual) in place on d_out — 1024 threads/block
// ---------------------------------------------------------------------------
__global__ __launch_bounds__(1024)
void gn_kernel(float* __restrict__ out, const float* __restrict__ Hand,
               const float* __restrict__ gw, const float* __restrict__ gb)
{
    const int b = blockIdx.x >> 5;
    const int g = blockIdx.x & 31;
    const size_t off = (size_t)b * CH * NPIX + (size_t)g * CPG * NPIX;
    float* base = out + off;
    const float* hb = Hand + off;
    const int tid = threadIdx.x;

    float s1 = 0.f, s2 = 0.f;
    #pragma unroll
    for (int i = 0; i < 8; ++i) {
        float4 v = *(const float4*)(base + i * 4096 + tid * 4);
        s1 += v.x + v.y + v.z + v.w;
        s2 += v.x * v.x + v.y * v.y + v.z * v.z + v.w * v.w;
    }
    s1 = warpSum(s1);
    s2 = warpSum(s2);
    __shared__ float a1[32], a2[32];
    if ((tid & 31) == 0) { a1[tid >> 5] = s1; a2[tid >> 5] = s2; }
    __syncthreads();
    __shared__ float mean_s, rstd_s;
    if (tid < 32) {
        float S1 = a1[tid], S2 = a2[tid];
        S1 = warpSum(S1);
        S2 = warpSum(S2);
        if (tid == 0) {
            const float inv  = 1.f / (float)(CPG * NPIX);
            const float mean = S1 * inv;
            const float var  = S2 * inv - mean * mean;
            mean_s = mean;
            rstd_s = rsqrtf(var + 1e-5f);
        }
    }
    __syncthreads();
    const float mean = mean_s, rstd = rstd_s;

    #pragma unroll
    for (int i = 0; i < 8; ++i) {
        const int f = i * 4096 + tid * 4;
        const int c = g * CPG + (f >> 12);
        const float w  = gw[c];
        const float bi = gb[c];
        float4 v = *(const float4*)(base + f);
        float4 h = *(const float4*)(hb + f);
        v.x = (v.x - mean) * rstd * w + bi + h.x;
        v.y = (v.y - mean) * rstd * w + bi + h.y;
        v.z = (v.z - mean) * rstd * w + bi + h.z;
        v.w = (v.w - mean) * rstd * w + bi + h.w;
        *(float4*)(base + f) = v;
    }
}

// ---------------------------------------------------------------------------
extern "C" void kernel_launch(void* const* d_in, const int* in_sizes, int n_in,
                              void* d_out, int out_size)
{
    const float* Hand = (const float*)d_in[0];
    const float* U    = (const float*)d_in[1];
    const float* WHw  = (const float*)d_in[2];
    const float* WHb  = (const float*)d_in[3];
    const float* WUw  = (const float*)d_in[4];
    const float* WUb  = (const float*)d_in[5];
    const float* gnw  = (const float*)d_in[6];
    const float* gnb  = (const float*)d_in[7];
    float* out = (float*)d_out;

    const int pj_smem = 6 * STG_BYTES;                      // 61440
    const int sg_smem = 6 * STG_BYTES + 128 * 4 * 4;        // 63488
    const int av_smem = 6 * STG_BYTES + 128 * 32 * 4;       // 77824
    cudaFuncSetAttribute(proj_f16,  cudaFuncAttributeMaxDynamicSharedMemorySize, pj_smem);
    cudaFuncSetAttribute(sgemm_f16, cudaFuncAttributeMaxDynamicSharedMemorySize, sg_smem);
    cudaFuncSetAttribute(av_f16,    cudaFuncAttributeMaxDynamicSharedMemorySize, av_smem);

    wconv_kernel<<<(2 * CH * CH) / (256 * 4), 256>>>(WHw, WUw);

    dim3 tg(NPIX / 32, CH / 32, BATCH * 2);
    tin_kernel<<<tg, 256>>>(Hand, U);

    dim3 pg(NPIX / 128, CH / 128, BATCH * 2);
    proj_f16<<<pg, 256, pj_smem>>>(WHb, WUb);

    dim3 sg(NPIX / 128, NPIX / 128, BATCH);
    sgemm_f16<<<sg, 256, sg_smem>>>();

    dim3 ag(NPIX / 128, CH / 128, BATCH);
    av_f16<<<ag, 256, av_smem>>>(out);

    gn_kernel<<<BATCH * NGRP, 1024>>>(out, Hand, gnw, gnb);
}

// round 17
// speedup vs baseline: 1.0531x; 1.0016x over previous
#include <cuda_runtime.h>
#include <cuda_fp16.h>
#include <cstdint>

#define BATCH 4
#define CH    256
#define NPIX  4096
#define NGRP  32
#define CPG   8

// ---------------------------------------------------------------------------
// Scratch (device globals)
// ---------------------------------------------------------------------------
__device__ __half g_ht[BATCH * NPIX * CH];           // Hand^T fp16 [b][n][c]
__device__ __half g_ut[BATCH * NPIX * CH];           // U^T    fp16 [b][n][c]
__device__ __half g_wh[CH * CH];                     // WH fp16 [o][c]
__device__ __half g_wu[CH * CH];                     // WU fp16 [o][c]
__device__ __half g_qt[BATCH * NPIX * CH];           // q^T fp16 [b][n][c]
__device__ __half g_kt[BATCH * NPIX * CH];           // k^T fp16 [b][m][c]
__device__ __half g_ub[BATCH * CH * NPIX];           // U fp16   [b][c][m]
__device__ __half g_P [(size_t)BATCH * NPIX * NPIX]; // exp(s - mx_tile) fp16
__device__ float  g_pmx  [BATCH * NPIX * 32];
__device__ float  g_psum [BATCH * NPIX * 32];

// ---------------------------------------------------------------------------
// Helpers
// ---------------------------------------------------------------------------
__device__ __forceinline__ float warpMax(float v) {
    #pragma unroll
    for (int o = 16; o > 0; o >>= 1)
        v = fmaxf(v, __shfl_xor_sync(0xffffffffu, v, o));
    return v;
}
__device__ __forceinline__ float warpSum(float v) {
    #pragma unroll
    for (int o = 16; o > 0; o >>= 1)
        v += __shfl_xor_sync(0xffffffffu, v, o);
    return v;
}
// fp16 m16n8k16, fp32 accumulate
__device__ __forceinline__ void mma_f16(float* c, const unsigned* a, const unsigned* b) {
    asm volatile(
        "mma.sync.aligned.m16n8k16.row.col.f32.f16.f16.f32 "
        "{%0,%1,%2,%3},{%4,%5,%6,%7},{%8,%9},{%0,%1,%2,%3};"
        : "+f"(c[0]), "+f"(c[1]), "+f"(c[2]), "+f"(c[3])
        : "r"(a[0]), "r"(a[1]), "r"(a[2]), "r"(a[3]), "r"(b[0]), "r"(b[1]));
}
__device__ __forceinline__ void ldsm_x4(unsigned* r, uint32_t addr) {
    asm volatile("ldmatrix.sync.aligned.m8n8.x4.shared.b16 {%0,%1,%2,%3}, [%4];"
                 : "=r"(r[0]), "=r"(r[1]), "=r"(r[2]), "=r"(r[3]) : "r"(addr));
}
__device__ __forceinline__ uint32_t smem_u32(const void* p) {
    uint32_t a;
    asm("{ .reg .u64 t; cvta.to.shared.u64 t, %1; cvt.u32.u64 %0, t; }" : "=r"(a) : "l"(p));
    return a;
}
__device__ __forceinline__ void cpa16(uint32_t dst, const void* src) {
    asm volatile("cp.async.cg.shared.global [%0], [%1], 16;" :: "r"(dst), "l"(src));
}
#define CPA_COMMIT() asm volatile("cp.async.commit_group;" ::: "memory")
#define CPA_WAIT1()  asm volatile("cp.async.wait_group 1;" ::: "memory")
#define CPA_WAIT0()  asm volatile("cp.async.wait_group 0;" ::: "memory")

#define PW        40
#define STG_BYTES (128 * PW * 2)   // 10240 B per 128-row stage
#define LOG2E     1.4426950408889634f

// ---------------------------------------------------------------------------
// 0) Transpose inputs + fp16 convert: Hand/U [c][n] -> g_ht/g_ut [n][c]
//    For U (which==1), also emit the straight-layout fp16 copy (g_ub).
//    Weight conversion folded into the (z==0, y==0) slice (128 blocks).
// ---------------------------------------------------------------------------
__global__ __launch_bounds__(256)
void tin_kernel(const float* __restrict__ Hand, const float* __restrict__ U,
                const float* __restrict__ wh, const float* __restrict__ wu)
{
    __shared__ float t[32][33];
    const int which = blockIdx.z & 1;
    const int b     = blockIdx.z >> 1;

    // folded weight conversion: exactly 128 blocks x 256 threads x 4 floats
    if (blockIdx.z == 0 && blockIdx.y == 0) {
        const int i = (blockIdx.x * 256 + threadIdx.x) * 4;
        const float* src;
        __half* dst;
        int j = i;
        if (i < CH * CH) { src = wh; dst = g_wh; }
        else             { src = wu; dst = g_wu; j = i - CH * CH; }
        float4 v = *(const float4*)(src + j);
        __half2 h0 = __floats2half2_rn(v.x, v.y);
        __half2 h1 = __floats2half2_rn(v.z, v.w);
        uint2 w;
        w.x = *(unsigned*)&h0;
        w.y = *(unsigned*)&h1;
        *(uint2*)(dst + j) = w;
    }

    const float* src = which ? U : Hand;
    __half* dst = which ? g_ut : g_ht;

    const int n0 = blockIdx.x * 32;
    const int c0 = blockIdx.y * 32;
    const int tx = threadIdx.x & 31;
    const int ty = threadIdx.x >> 5;

    const float* sp = src + (size_t)b * CH * NPIX + (size_t)(c0 + ty) * NPIX + n0 + tx;
    #pragma unroll
    for (int j = 0; j < 4; ++j) {
        const float v = sp[(size_t)j * 8 * NPIX];
        t[ty + j * 8][tx] = v;
        if (which) {
            g_ub[(size_t)b * CH * NPIX + (size_t)(c0 + ty + j * 8) * NPIX + n0 + tx] =
                __float2half(v);
        }
    }
    __syncthreads();

    #pragma unroll
    for (int j = 0; j < 4; ++j) {
        size_t o = (size_t)b * NPIX * CH + (size_t)(n0 + ty + j * 8) * CH + c0 + tx;
        dst[o] = __float2half(t[tx][ty + j * 8]);
    }
}

// ---------------------------------------------------------------------------
// 1) Projection fp16 GEMM: dst[n][o] = Xt[n][:]·W[o][:] + bias[o]
//    Single launch: blockIdx.z = b + BATCH*which. 3-stage pipeline.
// ---------------------------------------------------------------------------
__global__ __launch_bounds__(256, 2)
void proj_f16(const float* __restrict__ biasH, const float* __restrict__ biasU)
{
    extern __shared__ char sm_[];
    __half* As = (__half*)sm_;
    __half* Bs = (__half*)(sm_ + 3 * STG_BYTES);

    const int which = blockIdx.z >> 2;
    const int b     = blockIdx.z & 3;
    const __half* xt = which ? g_ut : g_ht;
    const __half* wf = which ? g_wu : g_wh;
    const float* bias = which ? biasU : biasH;
    __half* dst = which ? g_kt : g_qt;

    const int o0 = blockIdx.y * 128;
    const int n0 = blockIdx.x * 128;
    const int tid  = threadIdx.x;
    const int lane = tid & 31;
    const int wid  = tid >> 5;
    const int wm   = (wid >> 2) * 64;   // n
    const int wn   = (wid & 3) * 32;    // o

    const int r  = tid >> 1;
    const int hb = (tid & 1) * 16;
    const __half* ag = xt + (size_t)b * NPIX * CH + (size_t)(n0 + r) * CH + hb;
    const __half* bg = wf + (size_t)(o0 + r) * CH + hb;
    const uint32_t as_ = smem_u32(As) + (uint32_t)(r * 80 + hb * 2);
    const uint32_t bs_ = smem_u32(Bs) + (uint32_t)(r * 80 + hb * 2);

    const uint32_t afrag = smem_u32(As)
        + (uint32_t)(((wm + (lane & 15)) * PW + ((lane >> 4) * 8)) * 2);
    const uint32_t bfrag = smem_u32(Bs)
        + (uint32_t)(((wn + ((lane & 16) >> 1) + (lane & 7)) * PW + (lane & 8)) * 2);

    const int KT = CH / 32;  // 8
    #define PJ_ISSUE(kt) do {                                   \
        const uint32_t so = (uint32_t)((kt) % 3) * STG_BYTES;   \
        cpa16(as_ + so,      ag + (kt) * 32);                   \
        cpa16(as_ + so + 16, ag + (kt) * 32 + 8);               \
        cpa16(bs_ + so,      bg + (kt) * 32);                   \
        cpa16(bs_ + so + 16, bg + (kt) * 32 + 8);               \
        CPA_COMMIT();                                           \
    } while (0)

    PJ_ISSUE(0);
    PJ_ISSUE(1);

    float acc[4][4][4];
    #pragma unroll
    for (int i = 0; i < 4; ++i)
        #pragma unroll
        for (int j = 0; j < 4; ++j)
            #pragma unroll
            for (int q = 0; q < 4; ++q) acc[i][j][q] = 0.f;

    #pragma unroll 1
    for (int kt = 0; kt < KT; ++kt) {
        if (kt + 1 < KT) { CPA_WAIT1(); } else { CPA_WAIT0(); }
        __syncthreads();
        if (kt + 2 < KT) PJ_ISSUE(kt + 2);

        const uint32_t so = (uint32_t)(kt % 3) * STG_BYTES;
        #pragma unroll
        for (int ks = 0; ks < 2; ++ks) {
            unsigned a[4][4], bb[4][2];
            const uint32_t ko = so + (uint32_t)ks * 32;
            #pragma unroll
            for (int mt = 0; mt < 4; ++mt)
                ldsm_x4(a[mt], afrag + ko + (uint32_t)mt * (16 * PW * 2));
            ldsm_x4(&bb[0][0], bfrag + ko);
            ldsm_x4(&bb[2][0], bfrag + ko + (uint32_t)(16 * PW * 2));
            #pragma unroll
            for (int mt = 0; mt < 4; ++mt)
                #pragma unroll
                for (int nt = 0; nt < 4; ++nt)
                    mma_f16(acc[mt][nt], a[mt], bb[nt]);
        }
    }
    #undef PJ_ISSUE

    const int fr = lane >> 2, fc = (lane & 3) * 2;
    __half* db = dst + (size_t)b * NPIX * CH;
    #pragma unroll
    for (int mt = 0; mt < 4; ++mt) {
        const int row = n0 + wm + mt * 16 + fr;
        #pragma unroll
        for (int nt = 0; nt < 4; ++nt) {
            const int col = o0 + wn + nt * 8 + fc;
            const float bv0 = bias[col];
            const float bv1 = bias[col + 1];
            __half2 h0 = __floats2half2_rn(acc[mt][nt][0] + bv0, acc[mt][nt][1] + bv1);
            __half2 h1 = __floats2half2_rn(acc[mt][nt][2] + bv0, acc[mt][nt][3] + bv1);
            *(__half2*)(db + (size_t)row * CH + col)       = h0;
            *(__half2*)(db + (size_t)(row + 8) * CH + col) = h1;
        }
    }
}

// ---------------------------------------------------------------------------
// 2) Logits GEMM fp16 (LDSM fragments) + fused per-tile softmax (ex2.f16x2)
// ---------------------------------------------------------------------------
__global__ __launch_bounds__(256, 2)
void sgemm_f16()
{
    extern __shared__ char sm_[];
    __half* Qs = (__half*)sm_;
    __half* Ks = (__half*)(sm_ + 3 * STG_BYTES);
    float*  red = (float*)(sm_ + 6 * STG_BYTES);   // [128][4]

    const int m0 = blockIdx.x * 128;
    const int n0 = blockIdx.y * 128;
    const int b  = blockIdx.z;
    const int tid  = threadIdx.x;
    const int lane = tid & 31;
    const int wid  = tid >> 5;
    const int wm   = (wid >> 2) * 64;
    const int wn   = (wid & 3) * 32;

    const int r  = tid >> 1;
    const int hb = (tid & 1) * 16;
    const __half* qg = g_qt + (size_t)b * NPIX * CH + (size_t)(n0 + r) * CH + hb;
    const __half* kg = g_kt + (size_t)b * NPIX * CH + (size_t)(m0 + r) * CH + hb;
    const uint32_t qs = smem_u32(Qs) + (uint32_t)(r * 80 + hb * 2);
    const uint32_t ks_ = smem_u32(Ks) + (uint32_t)(r * 80 + hb * 2);

    const uint32_t afrag = smem_u32(Qs)
        + (uint32_t)(((wm + (lane & 15)) * PW + ((lane >> 4) * 8)) * 2);
    const uint32_t bfrag = smem_u32(Ks)
        + (uint32_t)(((wn + ((lane & 16) >> 1) + (lane & 7)) * PW + (lane & 8)) * 2);

    const int KT = CH / 32;  // 8 stages
    #define SG_ISSUE(kt) do {                                   \
        const uint32_t so = (uint32_t)((kt) % 3) * STG_BYTES;   \
        cpa16(qs + so,      qg + (kt) * 32);                    \
        cpa16(qs + so + 16, qg + (kt) * 32 + 8);                \
        cpa16(ks_ + so,      kg + (kt) * 32);                   \
        cpa16(ks_ + so + 16, kg + (kt) * 32 + 8);               \
        CPA_COMMIT();                                           \
    } while (0)

    SG_ISSUE(0);
    SG_ISSUE(1);

    float acc[4][4][4];
    #pragma unroll
    for (int i = 0; i < 4; ++i)
        #pragma unroll
        for (int j = 0; j < 4; ++j)
            #pragma unroll
            for (int q = 0; q < 4; ++q) acc[i][j][q] = 0.f;

    #pragma unroll 1
    for (int kt = 0; kt < KT; ++kt) {
        if (kt + 1 < KT) { CPA_WAIT1(); } else { CPA_WAIT0(); }
        __syncthreads();
        if (kt + 2 < KT) SG_ISSUE(kt + 2);

        const uint32_t so = (uint32_t)(kt % 3) * STG_BYTES;
        #pragma unroll
        for (int ks = 0; ks < 2; ++ks) {
            unsigned a[4][4], bb[4][2];
            const uint32_t ko = so + (uint32_t)ks * 32;
            #pragma unroll
            for (int mt = 0; mt < 4; ++mt)
                ldsm_x4(a[mt], afrag + ko + (uint32_t)mt * (16 * PW * 2));
            ldsm_x4(&bb[0][0], bfrag + ko);
            ldsm_x4(&bb[2][0], bfrag + ko + (uint32_t)(16 * PW * 2));
            #pragma unroll
            for (int mt = 0; mt < 4; ++mt)
                #pragma unroll
                for (int nt = 0; nt < 4; ++nt)
                    mma_f16(acc[mt][nt], a[mt], bb[nt]);
        }
    }
    #undef SG_ISSUE

    // ---- fused tile softmax ----
    float rmax[8];
    #pragma unroll
    for (int mt = 0; mt < 4; ++mt)
        #pragma unroll
        for (int h = 0; h < 2; ++h) {
            float v = fmaxf(acc[mt][0][h * 2], acc[mt][0][h * 2 + 1]);
            #pragma unroll
            for (int nt = 1; nt < 4; ++nt)
                v = fmaxf(v, fmaxf(acc[mt][nt][h * 2], acc[mt][nt][h * 2 + 1]));
            rmax[mt * 2 + h] = v;
        }
    #pragma unroll
    for (int s = 0; s < 8; ++s) {
        rmax[s] = fmaxf(rmax[s], __shfl_xor_sync(0xffffffffu, rmax[s], 1));
        rmax[s] = fmaxf(rmax[s], __shfl_xor_sync(0xffffffffu, rmax[s], 2));
    }
    __syncthreads();
    if ((lane & 3) == 0) {
        #pragma unroll
        for (int s = 0; s < 8; ++s) {
            const int rr = wm + (s >> 1) * 16 + (lane >> 2) + (s & 1) * 8;
            red[rr * 4 + (wid & 3)] = rmax[s];
        }
    }
    __syncthreads();
    float tmax[8];
    #pragma unroll
    for (int s = 0; s < 8; ++s) {
        const int rr = wm + (s >> 1) * 16 + (lane >> 2) + (s & 1) * 8;
        tmax[s] = fmaxf(fmaxf(red[rr * 4], red[rr * 4 + 1]),
                        fmaxf(red[rr * 4 + 2], red[rr * 4 + 3]));
    }
    __syncthreads();

    // exp via packed half2 ex2: p = 2^((s - max) * log2e)
    float rsum[8] = {0.f, 0.f, 0.f, 0.f, 0.f, 0.f, 0.f, 0.f};
    #pragma unroll
    for (int mt = 0; mt < 4; ++mt)
        #pragma unroll
        for (int h = 0; h < 2; ++h) {
            const int slot = mt * 2 + h;
            const int rr = wm + mt * 16 + (lane >> 2) + h * 8;
            const float tmL = tmax[slot] * LOG2E;
            __half* pp = g_P + (size_t)b * NPIX * NPIX
                       + (size_t)(n0 + rr) * NPIX + m0 + wn + (lane & 3) * 2;
            #pragma unroll
            for (int nt = 0; nt < 4; ++nt) {
                const float t0 = fmaf(acc[mt][nt][h * 2],     LOG2E, -tmL);
                const float t1 = fmaf(acc[mt][nt][h * 2 + 1], LOG2E, -tmL);
                __half2 th = __floats2half2_rn(t0, t1);
                unsigned pu;
                asm("ex2.approx.f16x2 %0, %1;" : "=r"(pu) : "r"(*(unsigned*)&th));
                __half2 ph = *(__half2*)&pu;
                float2 pf = __half22float2(ph);
                rsum[slot] += pf.x + pf.y;
                *(__half2*)(pp + nt * 8) = ph;
            }
        }
    #pragma unroll
    for (int s = 0; s < 8; ++s) {
        rsum[s] += __shfl_xor_sync(0xffffffffu, rsum[s], 1);
        rsum[s] += __shfl_xor_sync(0xffffffffu, rsum[s], 2);
    }
    if ((lane & 3) == 0) {
        #pragma unroll
        for (int s = 0; s < 8; ++s) {
            const int rr = wm + (s >> 1) * 16 + (lane >> 2) + (s & 1) * 8;
            red[rr * 4 + (wid & 3)] = rsum[s];
        }
    }
    __syncthreads();
    if ((wid & 3) == 0 && (lane & 3) == 0) {
        #pragma unroll
        for (int s = 0; s < 8; ++s) {
            const int rr = wm + (s >> 1) * 16 + (lane >> 2) + (s & 1) * 8;
            const float tot = red[rr * 4] + red[rr * 4 + 1] + red[rr * 4 + 2] + red[rr * 4 + 3];
            const int gi = (b * NPIX + n0 + rr) * 32 + blockIdx.x;
            g_pmx[gi]  = tmax[s];
            g_psum[gi] = tot;
        }
    }
}

// ---------------------------------------------------------------------------
// 3) AV GEMM fp16 (LDSM fragments). 3-stage pipeline.
//    Combine folded into prologue: batched loads + interleaved shuffle chains.
// ---------------------------------------------------------------------------
__global__ __launch_bounds__(256, 2)
void av_f16(float* __restrict__ out)
{
    extern __shared__ char sm_[];
    __half* Us = (__half*)sm_;
    __half* Ps = (__half*)(sm_ + 3 * STG_BYTES);
    float*  scs = (float*)(sm_ + 6 * STG_BYTES);   // [128][32] scales

    const int n0 = blockIdx.x * 128;
    const int c0 = blockIdx.y * 128;
    const int b  = blockIdx.z;
    const int tid  = threadIdx.x;
    const int lane = tid & 31;
    const int wid  = tid >> 5;
    const int wm   = (wid >> 2) * 64;
    const int wn   = (wid & 3) * 32;

    const int r  = tid >> 1;
    const int hb = (tid & 1) * 16;
    const __half* ug = g_ub + (size_t)b * CH * NPIX   + (size_t)(c0 + r) * NPIX + hb;
    const __half* pg = g_P  + (size_t)b * NPIX * NPIX + (size_t)(n0 + r) * NPIX + hb;
    const uint32_t us = smem_u32(Us) + (uint32_t)(r * 80 + hb * 2);
    const uint32_t ps = smem_u32(Ps) + (uint32_t)(r * 80 + hb * 2);

    const uint32_t afrag = smem_u32(Us)
        + (uint32_t)(((wm + (lane & 15)) * PW + ((lane >> 4) * 8)) * 2);
    const uint32_t bfrag = smem_u32(Ps)
        + (uint32_t)(((wn + ((lane & 16) >> 1) + (lane & 7)) * PW + (lane & 8)) * 2);

    const int KT = NPIX / 32;  // 128 stages
    #define AV_ISSUE(kt) do {                                   \
        const uint32_t so = (uint32_t)((kt) % 3) * STG_BYTES;   \
        cpa16(us + so,      ug + (kt) * 32);                    \
        cpa16(us + so + 16, ug + (kt) * 32 + 8);                \
        cpa16(ps + so,      pg + (kt) * 32);                    \
        cpa16(ps + so + 16, pg + (kt) * 32 + 8);                \
        CPA_COMMIT();                                           \
    } while (0)

    AV_ISSUE(0);
    AV_ISSUE(1);

    // inline combine (exact arithmetic of old combine_kernel) — batched
    #pragma unroll
    for (int g = 0; g < 2; ++g) {
        float mx[8], sm[8];
        #pragma unroll
        for (int i = 0; i < 8; ++i) {
            const int row = wid * 16 + g * 8 + i;
            const int gi = (b * NPIX + n0 + row) * 32 + lane;
            mx[i] = g_pmx[gi];
            sm[i] = g_psum[gi];
        }
        float M[8];
        #pragma unroll
        for (int i = 0; i < 8; ++i) M[i] = mx[i];
        #pragma unroll
        for (int o = 16; o > 0; o >>= 1)
            #pragma unroll
            for (int i = 0; i < 8; ++i)
                M[i] = fmaxf(M[i], __shfl_xor_sync(0xffffffffu, M[i], o));
        float e[8], tot[8];
        #pragma unroll
        for (int i = 0; i < 8; ++i) {
            e[i]   = __expf(mx[i] - M[i]);
            tot[i] = sm[i] * e[i];
        }
        #pragma unroll
        for (int o = 16; o > 0; o >>= 1)
            #pragma unroll
            for (int i = 0; i < 8; ++i)
                tot[i] += __shfl_xor_sync(0xffffffffu, tot[i], o);
        #pragma unroll
        for (int i = 0; i < 8; ++i) {
            const int row = wid * 16 + g * 8 + i;
            scs[row * 32 + lane] = e[i] / tot[i];
        }
    }
    __syncthreads();

    float acc[4][4][4];
    #pragma unroll
    for (int i = 0; i < 4; ++i)
        #pragma unroll
        for (int j = 0; j < 4; ++j)
            #pragma unroll
            for (int q = 0; q < 4; ++q) acc[i][j][q] = 0.f;

    __half2 sc[4];

    #pragma unroll 1
    for (int kt = 0; kt < KT; ++kt) {
        if ((kt & 3) == 0) {
            #pragma unroll
            for (int nt = 0; nt < 4; ++nt) {
                const int n = wn + nt * 8 + (lane >> 2);
                sc[nt] = __float2half2_rn(scs[n * 32 + (kt >> 2)]);
            }
        }
        if (kt + 1 < KT) { CPA_WAIT1(); } else { CPA_WAIT0(); }
        __syncthreads();
        if (kt + 2 < KT) AV_ISSUE(kt + 2);

        const uint32_t so = (uint32_t)(kt % 3) * STG_BYTES;
        #pragma unroll
        for (int ks = 0; ks < 2; ++ks) {
            unsigned a[4][4], bb[4][2];
            const uint32_t ko = so + (uint32_t)ks * 32;
            #pragma unroll
            for (int mt = 0; mt < 4; ++mt)
                ldsm_x4(a[mt], afrag + ko + (uint32_t)mt * (16 * PW * 2));
            ldsm_x4(&bb[0][0], bfrag + ko);
            ldsm_x4(&bb[2][0], bfrag + ko + (uint32_t)(16 * PW * 2));
            #pragma unroll
            for (int nt = 0; nt < 4; ++nt) {
                __half2 b0 = __hmul2(*(__half2*)&bb[nt][0], sc[nt]);
                __half2 b1 = __hmul2(*(__half2*)&bb[nt][1], sc[nt]);
                bb[nt][0] = *(unsigned*)&b0;
                bb[nt][1] = *(unsigned*)&b1;
            }
            #pragma unroll
            for (int mt = 0; mt < 4; ++mt)
                #pragma unroll
                for (int nt = 0; nt < 4; ++nt)
                    mma_f16(acc[mt][nt], a[mt], bb[nt]);
        }
    }
    #undef AV_ISSUE

    const int fr = lane >> 2, fc = (lane & 3) * 2;
    #pragma unroll
    for (int mt = 0; mt < 4; ++mt) {
        const int row = c0 + wm + mt * 16 + fr;
        #pragma unroll
        for (int nt = 0; nt < 4; ++nt) {
            const int col = n0 + wn + nt * 8 + fc;
            float* p0 = out + (size_t)b * CH * NPIX + (size_t)row * NPIX + col;
            float* p1 = p0 + (size_t)8 * NPIX;
            *(float2*)p0 = make_float2(acc[mt][nt][0], acc[mt][nt][1]);
            *(float2*)p1 = make_float2(acc[mt][nt][2], acc[mt][nt][3]);
        }
    }
}

// ---------------------------------------------------------------------------
// 4) GroupNorm(+residual), single-pass: group slab buffered in smem.
//    1024 threads, 128 KB dynamic smem, one block per (b, group).
// ---------------------------------------------------------------------------
__global__ __launch_bounds__(1024)
void gn_kernel(float* __restrict__ out, const float* __restrict__ Hand,
               const float* __restrict__ gw, const float* __restrict__ gb)
{
    extern __shared__ float buf[];   // 32768 floats = 128 KB
    const int b = blockIdx.x >> 5;
    const int g = blockIdx.x & 31;
    const size_t off = (size_t)b * CH * NPIX + (size_t)g * CPG * NPIX;
    float* base = out + off;
    const float* hb = Hand + off;
    const int tid = threadIdx.x;

    float s1 = 0.f, s2 = 0.f;
    #pragma unroll
    for (int i = 0; i < 8; ++i) {
        const int f = i * 4096 + tid * 4;
        float4 v = *(const float4*)(base + f);
        *(float4*)(buf + f) = v;
        s1 += v.x + v.y + v.z + v.w;
        s2 += v.x * v.x + v.y * v.y + v.z * v.z + v.w * v.w;
    }
    s1 = warpSum(s1);
    s2 = warpSum(s2);
    __shared__ float a1[32], a2[32];
    if ((tid & 31) == 0) { a1[tid >> 5] = s1; a2[tid >> 5] = s2; }
    __syncthreads();
    __shared__ float mean_s, rstd_s;
    if (tid < 32) {
        float S1 = a1[tid], S2 = a2[tid];
        S1 = warpSum(S1);
        S2 = warpSum(S2);
        if (tid == 0) {
            const float inv  = 1.f / (float)(CPG * NPIX);
            const float mean = S1 * inv;
            const float var  = S2 * inv - mean * mean;
            mean_s = mean;
            rstd_s = rsqrtf(var + 1e-5f);
        }
    }
    __syncthreads();
    const float mean = mean_s, rstd = rstd_s;

    #pragma unroll
    for (int i = 0; i < 8; ++i) {
        const int f = i * 4096 + tid * 4;
        const int c = g * CPG + (f >> 12);
        const float w  = gw[c];
        const float bi = gb[c];
        float4 v = *(const float4*)(buf + f);
        float4 h = *(const float4*)(hb + f);
        v.x = (v.x - mean) * rstd * w + bi + h.x;
        v.y = (v.y - mean) * rstd * w + bi + h.y;
        v.z = (v.z - mean) * rstd * w + bi + h.z;
        v.w = (v.w - mean) * rstd * w + bi + h.w;
        *(float4*)(base + f) = v;
    }
}

// ---------------------------------------------------------------------------
extern "C" void kernel_launch(void* const* d_in, const int* in_sizes, int n_in,
                              void* d_out, int out_size)
{
    const float* Hand = (const float*)d_in[0];
    const float* U    = (const float*)d_in[1];
    const float* WHw  = (const float*)d_in[2];
    const float* WHb  = (const float*)d_in[3];
    const float* WUw  = (const float*)d_in[4];
    const float* WUb  = (const float*)d_in[5];
    const float* gnw  = (const float*)d_in[6];
    const float* gnb  = (const float*)d_in[7];
    float* out = (float*)d_out;

    const int pj_smem = 6 * STG_BYTES;                      // 61440
    const int sg_smem = 6 * STG_BYTES + 128 * 4 * 4;        // 63488
    const int av_smem = 6 * STG_BYTES + 128 * 32 * 4;       // 77824
    const int gn_smem = CPG * NPIX * 4;                     // 131072
    cudaFuncSetAttribute(proj_f16,  cudaFuncAttributeMaxDynamicSharedMemorySize, pj_smem);
    cudaFuncSetAttribute(sgemm_f16, cudaFuncAttributeMaxDynamicSharedMemorySize, sg_smem);
    cudaFuncSetAttribute(av_f16,    cudaFuncAttributeMaxDynamicSharedMemorySize, av_smem);
    cudaFuncSetAttribute(gn_kernel, cudaFuncAttributeMaxDynamicSharedMemorySize, gn_smem);

    dim3 tg(NPIX / 32, CH / 32, BATCH * 2);
    tin_kernel<<<tg, 256>>>(Hand, U, WHw, WUw);

    dim3 pg(NPIX / 128, CH / 128, BATCH * 2);
    proj_f16<<<pg, 256, pj_smem>>>(WHb, WUb);

    dim3 sg(NPIX / 128, NPIX / 128, BATCH);
    sgemm_f16<<<sg, 256, sg_smem>>>();

    dim3 ag(NPIX / 128, CH / 128, BATCH);
    av_f16<<<ag, 256, av_smem>>>(out);

    gn_kernel<<<BATCH * NGRP, 1024, gn_smem>>>(out, Hand, gnw, gnb);
}